// round 1
// baseline (speedup 1.0000x reference)
#include <cuda_runtime.h>
#include <math.h>
#include <stdint.h>

// Problem constants (hardcoded per reference)
#define BB   2
#define HH   128
#define WWID 128
#define CC   128
#define NSW  8
#define WINH 16
#define NWIN 64            // windows per batch image
#define WSZ  256           // tokens per window
#define LTOK (HH*WWID)     // 16384
#define ROWS (BB*LTOK)     // 32768
#define HIDN 1024

// ---------------- scratch (static device arrays; no runtime allocation) ----
__device__ float g_Sg[ROWS*CC];      // windowed source
__device__ float g_Tg[ROWS*CC];      // windowed target
__device__ float g_QW[ROWS*CC];
__device__ float g_KW[ROWS*CC];
__device__ float g_VW[ROWS*CC];
__device__ float g_ATT[ROWS*CC];     // attention output (windowed layout)
__device__ float g_MSG[ROWS*CC];     // ATT @ Wm (windowed layout)
__device__ float g_FIN[(size_t)ROWS*2*CC];   // concat(source, LN(msg)) token layout
__device__ float g_HID[(size_t)ROWS*HIDN];   // gelu(FIN@W1)
__device__ float g_MSG2[ROWS*CC];    // HID @ W2 (token layout)

// ---------------- permutation: token layout -> shifted-window layout -------
__global__ __launch_bounds__(256) void perm_kernel(const float* __restrict__ src,
                                                   const float* __restrict__ tgt)
{
    int warp = (blockIdx.x * 256 + threadIdx.x) >> 5;
    int lane = threadIdx.x & 31;
    if (warp >= ROWS) return;
    int b   = warp >> 14;            // / 16384
    int wr  = warp & 16383;
    int win = wr >> 8;
    int pos = wr & 255;
    int ip = ((win >> 3) << 4) + (pos >> 4);   // shifted coords
    int jp = ((win & 7) << 4) + (pos & 15);
    int i = (ip + 8) & 127;                    // source token coords (roll -8)
    int j = (jp + 8) & 127;
    size_t srow = ((size_t)b * LTOK + (size_t)i * WWID + j) * CC;
    size_t drow = (size_t)warp * CC;
    const float4* s4 = (const float4*)(src + srow);
    const float4* t4 = (const float4*)(tgt + srow);
    ((float4*)(g_Sg + drow))[lane] = s4[lane];
    ((float4*)(g_Tg + drow))[lane] = t4[lane];
}

// ---------------- SGEMM: C[M,N] = A[M,K] @ B[K,N], optional exact GELU -----
__device__ __forceinline__ float gelu_exact(float x) {
    return 0.5f * x * (1.0f + erff(x * 0.70710678118654752f));
}

// 64x64 tile, BK=16, 256 threads, 4x4 microtile
__global__ __launch_bounds__(256) void sgemm64(const float* __restrict__ A,
                                               const float* __restrict__ B,
                                               float* __restrict__ C,
                                               int M, int N, int K, int act)
{
    __shared__ float As[16 * 68];   // [k][m], padded
    __shared__ float Bs[16 * 64];   // [k][n]
    int tid = threadIdx.x;
    int tx = tid & 15, ty = tid >> 4;
    int m0 = blockIdx.y * 64, n0 = blockIdx.x * 64;

    const int ar = tid >> 2;              // A loader row (0..63)
    const int as = (tid & 3) * 4;         // A loader k offset
    const int br = tid >> 4;              // B loader k row (0..15)
    const int bc = (tid & 15) * 4;        // B loader col

    float acc[4][4] = {};

    for (int kt = 0; kt < K; kt += 16) {
        float4 av = *(const float4*)(A + (size_t)(m0 + ar) * K + kt + as);
        float4 bv = *(const float4*)(B + (size_t)(kt + br) * N + n0 + bc);
        As[(as + 0) * 68 + ar] = av.x;
        As[(as + 1) * 68 + ar] = av.y;
        As[(as + 2) * 68 + ar] = av.z;
        As[(as + 3) * 68 + ar] = av.w;
        *(float4*)(Bs + br * 64 + bc) = bv;
        __syncthreads();
        #pragma unroll
        for (int kk = 0; kk < 16; kk++) {
            float4 a = *(const float4*)(As + kk * 68 + ty * 4);
            float4 b = *(const float4*)(Bs + kk * 64 + tx * 4);
            acc[0][0] += a.x * b.x; acc[0][1] += a.x * b.y; acc[0][2] += a.x * b.z; acc[0][3] += a.x * b.w;
            acc[1][0] += a.y * b.x; acc[1][1] += a.y * b.y; acc[1][2] += a.y * b.z; acc[1][3] += a.y * b.w;
            acc[2][0] += a.z * b.x; acc[2][1] += a.z * b.y; acc[2][2] += a.z * b.z; acc[2][3] += a.z * b.w;
            acc[3][0] += a.w * b.x; acc[3][1] += a.w * b.y; acc[3][2] += a.w * b.z; acc[3][3] += a.w * b.w;
        }
        __syncthreads();
    }

    #pragma unroll
    for (int i = 0; i < 4; i++) {
        float4 r = make_float4(acc[i][0], acc[i][1], acc[i][2], acc[i][3]);
        if (act) {
            r.x = gelu_exact(r.x); r.y = gelu_exact(r.y);
            r.z = gelu_exact(r.z); r.w = gelu_exact(r.w);
        }
        *(float4*)(C + (size_t)(m0 + ty * 4 + i) * N + n0 + tx * 4) = r;
    }
}

// ---------------- windowed attention ---------------------------------------
// block = half a window (128 query rows), 256 threads (2 per row, interleaved
// 4-float head-dim groups). smem: scores[128][257] + K tile + V tile + ids.
#define SD 257
#define ATTN_SMEM_FLOATS (128*SD + 64*128 + 64*128 + 256)
#define ATTN_SMEM_BYTES  (ATTN_SMEM_FLOATS*4)

__device__ __forceinline__ int region3(int x) { return (x < 112) ? 0 : ((x < 120) ? 1 : 2); }

__global__ __launch_bounds__(256) void attn_kernel()
{
    extern __shared__ float sm[];
    float* Ssh = sm;                     // 128*257
    float* Kt  = sm + 128 * SD;          // 64*128
    float* Vt  = Kt + 64 * 128;          // 64*128
    float* ids = Vt + 64 * 128;          // 256

    int t    = threadIdx.x;
    int wb   = blockIdx.x >> 1;          // global window (b*64 + win)
    int half = blockIdx.x & 1;
    int row  = t >> 1;                   // 0..127 local query row
    int part = t & 1;                    // head-dim interleave group
    int qrow = half * 128 + row;

    int win = wb & 63;
    int wr = win >> 3, wc = win & 7;

    // region ids for all 256 window positions
    {
        int pr = t >> 4, pc = t & 15;
        int i = wr * 16 + pr, j = wc * 16 + pc;
        ids[t] = (float)(region3(i) * 3 + region3(j));
    }
    int qpr = qrow >> 4, qpc = qrow & 15;
    float idq = (float)(region3(wr * 16 + qpr) * 3 + region3(wc * 16 + qpc));

    size_t base = (size_t)wb * WSZ * CC;

    // load this thread's 64 head-dims of q: groups {8g + 4*part + 0..3}
    float4 qv[16];
    {
        const float* qp = g_QW + base + (size_t)qrow * CC + part * 4;
        #pragma unroll
        for (int g = 0; g < 16; g++) qv[g] = *(const float4*)(qp + g * 8);
    }

    float mloc = -1e30f;
    __syncthreads();   // ids visible

    // ---- pass 1: scores ----
    for (int kt4 = 0; kt4 < 4; kt4++) {
        const float4* kg = (const float4*)(g_KW + base + (size_t)kt4 * 64 * CC);
        #pragma unroll
        for (int w = 0; w < 8; w++) ((float4*)Kt)[t + w * 256] = kg[t + w * 256];
        __syncthreads();
        #pragma unroll 2
        for (int j = 0; j < 64; j++) {
            const float* kp = Kt + j * CC + part * 4;
            float sp = 0.f;
            #pragma unroll
            for (int g = 0; g < 16; g++) {
                float4 kv = *(const float4*)(kp + g * 8);
                sp += qv[g].x * kv.x + qv[g].y * kv.y + qv[g].z * kv.z + qv[g].w * kv.w;
            }
            float s = sp + __shfl_xor_sync(0xffffffffu, sp, 1);
            int kj = kt4 * 64 + j;
            s = s * 0.08838834764831845f + ((idq != ids[kj]) ? -100.0f : 0.0f);
            if (part == 0) Ssh[row * SD + kj] = s;
            mloc = fmaxf(mloc, s);
        }
        __syncthreads();
    }

    // ---- pass 2: softmax (each partner handles half the key range) ----
    float sum = 0.f;
    {
        float* sr = Ssh + row * SD + part * 128;
        #pragma unroll 4
        for (int jj = 0; jj < 128; jj++) {
            float p = __expf(sr[jj] - mloc);
            sr[jj] = p;
            sum += p;
        }
    }
    sum += __shfl_xor_sync(0xffffffffu, sum, 1);
    float inv = 1.0f / sum;
    __syncthreads();

    // ---- pass 3: P @ V ----
    float4 acc[16];
    #pragma unroll
    for (int g = 0; g < 16; g++) acc[g] = make_float4(0.f, 0.f, 0.f, 0.f);

    for (int kt4 = 0; kt4 < 4; kt4++) {
        const float4* vg = (const float4*)(g_VW + base + (size_t)kt4 * 64 * CC);
        #pragma unroll
        for (int w = 0; w < 8; w++) ((float4*)Vt)[t + w * 256] = vg[t + w * 256];
        __syncthreads();
        #pragma unroll 2
        for (int j = 0; j < 64; j++) {
            float p = Ssh[row * SD + kt4 * 64 + j];
            const float* vp = Vt + j * CC + part * 4;
            #pragma unroll
            for (int g = 0; g < 16; g++) {
                float4 v = *(const float4*)(vp + g * 8);
                acc[g].x += p * v.x; acc[g].y += p * v.y;
                acc[g].z += p * v.z; acc[g].w += p * v.w;
            }
        }
        __syncthreads();
    }

    float* op = g_ATT + base + (size_t)qrow * CC + part * 4;
    #pragma unroll
    for (int g = 0; g < 16; g++) {
        float4 r = acc[g];
        r.x *= inv; r.y *= inv; r.z *= inv; r.w *= inv;
        *(float4*)(op + g * 8) = r;
    }
}

// ---------------- LN(msg) + build concat(source, msg) ----------------------
__global__ __launch_bounds__(256) void ln_concat_kernel(const float* __restrict__ src,
                                                        const float* __restrict__ g1,
                                                        const float* __restrict__ b1)
{
    int warp = (blockIdx.x * 256 + threadIdx.x) >> 5;
    int lane = threadIdx.x & 31;
    if (warp >= ROWS) return;
    int b   = warp >> 14;
    int tok = warp & 16383;
    int i = tok >> 7, j = tok & 127;
    int ip = (i + 120) & 127;                 // inverse shift
    int jp = (j + 120) & 127;
    int win = ((ip >> 4) << 3) + (jp >> 4);
    int pos = ((ip & 15) << 4) + (jp & 15);
    size_t mrow = ((size_t)b * NWIN + win) * WSZ + pos;

    float4 mv = ((const float4*)(g_MSG + mrow * CC))[lane];
    float s  = mv.x + mv.y + mv.z + mv.w;
    float ss = mv.x * mv.x + mv.y * mv.y + mv.z * mv.z + mv.w * mv.w;
    #pragma unroll
    for (int o = 16; o > 0; o >>= 1) {
        s  += __shfl_xor_sync(0xffffffffu, s,  o);
        ss += __shfl_xor_sync(0xffffffffu, ss, o);
    }
    float mean = s * (1.0f / 128.0f);
    float var  = ss * (1.0f / 128.0f) - mean * mean;
    float r = rsqrtf(var + 1e-5f);
    float4 gv = ((const float4*)g1)[lane];
    float4 bv = ((const float4*)b1)[lane];
    float4 o4;
    o4.x = (mv.x - mean) * r * gv.x + bv.x;
    o4.y = (mv.y - mean) * r * gv.y + bv.y;
    o4.z = (mv.z - mean) * r * gv.z + bv.z;
    o4.w = (mv.w - mean) * r * gv.w + bv.w;

    size_t frow = (size_t)warp * (2 * CC);
    ((float4*)(g_FIN + frow + CC))[lane] = o4;
    ((float4*)(g_FIN + frow))[lane] = ((const float4*)(src + (size_t)warp * CC))[lane];
}

// ---------------- final LN + residual ---------------------------------------
__global__ __launch_bounds__(256) void ln_res_kernel(const float* __restrict__ src,
                                                     const float* __restrict__ g2,
                                                     const float* __restrict__ b2,
                                                     float* __restrict__ out)
{
    int warp = (blockIdx.x * 256 + threadIdx.x) >> 5;
    int lane = threadIdx.x & 31;
    if (warp >= ROWS) return;

    float4 mv = ((const float4*)(g_MSG2 + (size_t)warp * CC))[lane];
    float s  = mv.x + mv.y + mv.z + mv.w;
    float ss = mv.x * mv.x + mv.y * mv.y + mv.z * mv.z + mv.w * mv.w;
    #pragma unroll
    for (int o = 16; o > 0; o >>= 1) {
        s  += __shfl_xor_sync(0xffffffffu, s,  o);
        ss += __shfl_xor_sync(0xffffffffu, ss, o);
    }
    float mean = s * (1.0f / 128.0f);
    float var  = ss * (1.0f / 128.0f) - mean * mean;
    float r = rsqrtf(var + 1e-5f);
    float4 gv = ((const float4*)g2)[lane];
    float4 bv = ((const float4*)b2)[lane];
    float4 sv = ((const float4*)(src + (size_t)warp * CC))[lane];
    float4 o4;
    o4.x = sv.x + (mv.x - mean) * r * gv.x + bv.x;
    o4.y = sv.y + (mv.y - mean) * r * gv.y + bv.y;
    o4.z = sv.z + (mv.z - mean) * r * gv.z + bv.z;
    o4.w = sv.w + (mv.w - mean) * r * gv.w + bv.w;
    ((float4*)(out + (size_t)warp * CC))[lane] = o4;
}

// ---------------- host launcher ---------------------------------------------
extern "C" void kernel_launch(void* const* d_in, const int* in_sizes, int n_in,
                              void* d_out, int out_size)
{
    const float* src = (const float*)d_in[0];
    const float* tgt = (const float*)d_in[1];
    const float* Wq  = (const float*)d_in[2];
    const float* Wk  = (const float*)d_in[3];
    const float* Wv  = (const float*)d_in[4];
    const float* Wm  = (const float*)d_in[5];
    const float* g1  = (const float*)d_in[6];
    const float* b1  = (const float*)d_in[7];
    const float* W1  = (const float*)d_in[8];
    const float* W2  = (const float*)d_in[9];
    const float* g2  = (const float*)d_in[10];
    const float* b2  = (const float*)d_in[11];
    // d_in[12] (mask) unused: region ids recomputed in-kernel.

    float *Sg, *Tg, *QW, *KW, *VW, *ATT, *MSG, *FIN, *HIDp, *MSG2;
    cudaGetSymbolAddress((void**)&Sg,   g_Sg);
    cudaGetSymbolAddress((void**)&Tg,   g_Tg);
    cudaGetSymbolAddress((void**)&QW,   g_QW);
    cudaGetSymbolAddress((void**)&KW,   g_KW);
    cudaGetSymbolAddress((void**)&VW,   g_VW);
    cudaGetSymbolAddress((void**)&ATT,  g_ATT);
    cudaGetSymbolAddress((void**)&MSG,  g_MSG);
    cudaGetSymbolAddress((void**)&FIN,  g_FIN);
    cudaGetSymbolAddress((void**)&HIDp, g_HID);
    cudaGetSymbolAddress((void**)&MSG2, g_MSG2);

    cudaFuncSetAttribute(attn_kernel, cudaFuncAttributeMaxDynamicSharedMemorySize,
                         ATTN_SMEM_BYTES);

    // 1) shift + window partition of source/target
    perm_kernel<<<4096, 256>>>(src, tgt);

    // 2) Q/K/V projections (windowed row order)
    sgemm64<<<dim3(2, 512), 256>>>(Sg, Wq, QW, ROWS, 128, 128, 0);
    sgemm64<<<dim3(2, 512), 256>>>(Tg, Wk, KW, ROWS, 128, 128, 0);
    sgemm64<<<dim3(2, 512), 256>>>(Tg, Wv, VW, ROWS, 128, 128, 0);

    // 3) shifted-window attention (mask generated in-kernel)
    attn_kernel<<<2 * BB * NWIN, 256, ATTN_SMEM_BYTES>>>();

    // 4) message projection
    sgemm64<<<dim3(2, 512), 256>>>(ATT, Wm, MSG, ROWS, 128, 128, 0);

    // 5) LayerNorm(message) + un-shift gather + concat with source
    ln_concat_kernel<<<4096, 256>>>(src, g1, b1);

    // 6) FFN: gelu(FIN @ W1) @ W2
    sgemm64<<<dim3(16, 512), 256>>>(FIN, W1, HIDp, ROWS, HIDN, 2 * CC, 1);
    sgemm64<<<dim3(2, 512), 256>>>(HIDp, W2, MSG2, ROWS, 128, HIDN, 0);

    // 7) final LayerNorm + residual
    ln_res_kernel<<<4096, 256>>>(src, g2, b2, (float*)d_out);
}

// round 3
// speedup vs baseline: 2.2165x; 2.2165x over previous
#include <cuda_runtime.h>
#include <math.h>
#include <stdint.h>

// Problem constants
#define BB   2
#define HH   128
#define WWID 128
#define CC   128
#define NWIN 64
#define WSZ  256
#define LTOK (HH*WWID)     // 16384
#define ROWS (BB*LTOK)     // 32768
#define HIDN 1024

// ---------------- scratch ---------------------------------------------------
__device__ float g_Sg[ROWS*CC];
__device__ float g_Tg[ROWS*CC];
__device__ float g_QW[ROWS*CC];
__device__ float g_KW[ROWS*CC];
__device__ float g_VW[ROWS*CC];
__device__ float g_ATT[ROWS*CC];
__device__ float g_MSG[ROWS*CC];
__device__ float g_FIN[(size_t)ROWS*2*CC];
__device__ float g_HID[(size_t)ROWS*HIDN];
__device__ float g_MSG2[ROWS*CC];
// transposed weights [N, K]
__device__ float g_WqT[CC*CC];
__device__ float g_WkT[CC*CC];
__device__ float g_WvT[CC*CC];
__device__ float g_WmT[CC*CC];
__device__ float g_W1T[HIDN*2*CC];
__device__ float g_W2T[CC*HIDN];

// ---------------- helpers ---------------------------------------------------
__device__ __forceinline__ float rtf32(float x) {
    float y; asm("cvt.rna.tf32.f32 %0, %1;" : "=f"(y) : "f"(x)); return y;
}
__device__ __forceinline__ float gelu_exact(float x) {
    return 0.5f * x * (1.0f + erff(x * 0.70710678118654752f));
}
__device__ __forceinline__ uint32_t smem_u32(const void* p) {
    uint32_t a;
    asm("{ .reg .u64 t; cvta.to.shared.u64 t, %1; cvt.u32.u64 %0, t; }" : "=r"(a) : "l"(p));
    return a;
}
__device__ __forceinline__ void cpasync16(uint32_t dst, const float* src) {
    asm volatile("cp.async.cg.shared.global [%0], [%1], 16;" :: "r"(dst), "l"(src));
}
__device__ __forceinline__ void ldmx4(uint32_t addr, uint32_t& d0, uint32_t& d1,
                                      uint32_t& d2, uint32_t& d3) {
    asm volatile("ldmatrix.sync.aligned.m8n8.x4.shared.b16 {%0,%1,%2,%3}, [%4];"
                 : "=r"(d0), "=r"(d1), "=r"(d2), "=r"(d3) : "r"(addr));
}
__device__ __forceinline__ void mma_tf32(float* c, const uint32_t* a, uint32_t b0, uint32_t b1) {
    asm volatile("mma.sync.aligned.m16n8k8.row.col.f32.tf32.tf32.f32 "
                 "{%0,%1,%2,%3}, {%4,%5,%6,%7}, {%8,%9}, {%0,%1,%2,%3};"
                 : "+f"(c[0]), "+f"(c[1]), "+f"(c[2]), "+f"(c[3])
                 : "r"(a[0]), "r"(a[1]), "r"(a[2]), "r"(a[3]), "r"(b0), "r"(b1));
}

// ---------------- weight transpose (round to tf32) --------------------------
__global__ __launch_bounds__(256) void transpose32(const float* __restrict__ in,
                                                   float* __restrict__ out, int R, int C)
{
    __shared__ float t[32][33];
    int bx = blockIdx.x * 32, by = blockIdx.y * 32;
    int x = bx + threadIdx.x;
    #pragma unroll
    for (int i = 0; i < 32; i += 8)
        t[threadIdx.y + i][threadIdx.x] = in[(size_t)(by + threadIdx.y + i) * C + x];
    __syncthreads();
    int x2 = by + threadIdx.x;
    #pragma unroll
    for (int i = 0; i < 32; i += 8)
        out[(size_t)(bx + threadIdx.y + i) * R + x2] = rtf32(t[threadIdx.x][threadIdx.y + i]);
}

// ---------------- tf32 mma.sync GEMM: C[M,N] = A[M,K] @ Bt[N,K]^T -----------
// 128x128x32 CTA tile, 8 warps (4m x 2n), warp tile 32x64, m16n8k8.
// smem rows padded to 36 floats (ldmatrix phase banks = 4r mod 32: conflict-free)
#define PADK 36
#define TILE_BYTES (128*PADK*4)     // 18432
#define SA0 0
#define SA1 TILE_BYTES
#define SB0 (2*TILE_BYTES)
#define SB1 (3*TILE_BYTES)
#define GSM_TOTAL (4*TILE_BYTES)    // 73728

__device__ __forceinline__ void load_tile(uint32_t sbase, const float* __restrict__ G,
                                          int ld, size_t row0, int col0, int tid)
{
    int r = tid >> 3, c4 = (tid & 7) * 4;
    #pragma unroll
    for (int i = 0; i < 4; i++) {
        int row = i * 32 + r;
        cpasync16(sbase + (uint32_t)((row * PADK + c4) * 4),
                  G + (row0 + row) * (size_t)ld + col0 + c4);
    }
}

__global__ __launch_bounds__(256) void gemm_tc(const float* __restrict__ A,
                                               const float* __restrict__ Bt,
                                               float* __restrict__ C,
                                               int M, int N, int K, int act)
{
    extern __shared__ char smem[];
    uint32_t sb = smem_u32(smem);
    int tid = threadIdx.x, wid = tid >> 5, lane = tid & 31;
    int wm = wid & 3, wn = wid >> 2;
    size_t m0 = (size_t)blockIdx.y * 128;
    int n0 = blockIdx.x * 128;
    const int nk = K >> 5;

    float acc[2][8][4];
    #pragma unroll
    for (int mt = 0; mt < 2; mt++)
        #pragma unroll
        for (int nt = 0; nt < 8; nt++)
            #pragma unroll
            for (int i = 0; i < 4; i++) acc[mt][nt][i] = 0.f;

    // precomputed ldmatrix lane addressing
    int mat = lane >> 3, mr = lane & 7;
    // A: matrices {rows0-7,k0-3},{rows8-15,k0-3},{rows0-7,k4-7},{rows8-15,k4-7}
    int a_row = wm * 32 + (mat & 1) * 8 + mr;
    int a_kc  = (mat >> 1) * 4;
    // B: matrices {n0-7,k0-3},{n0-7,k4-7},{n8-15,k0-3},{n8-15,k4-7}
    int b_n  = wn * 64 + (mat >> 1) * 8 + mr;
    int b_kc = (mat & 1) * 4;

    load_tile(sb + SA0, A, K, m0, 0, tid);
    load_tile(sb + SB0, Bt, K, (size_t)n0, 0, tid);
    asm volatile("cp.async.commit_group;");

    for (int kt = 0; kt < nk; kt++) {
        int b = kt & 1;
        if (kt + 1 < nk) {
            load_tile(sb + (b ? SA0 : SA1), A, K, m0, (kt + 1) * 32, tid);
            load_tile(sb + (b ? SB0 : SB1), Bt, K, (size_t)n0, (kt + 1) * 32, tid);
            asm volatile("cp.async.commit_group;");
            asm volatile("cp.async.wait_group 1;");
        } else {
            asm volatile("cp.async.wait_group 0;");
        }
        __syncthreads();

        uint32_t sA = sb + (b ? SA1 : SA0);
        uint32_t sB = sb + (b ? SB1 : SB0);
        #pragma unroll
        for (int ks = 0; ks < 4; ks++) {
            uint32_t a[2][4], bb[4][4];
            #pragma unroll
            for (int mt = 0; mt < 2; mt++)
                ldmx4(sA + (uint32_t)(((a_row + mt * 16) * PADK + ks * 8 + a_kc) * 4),
                      a[mt][0], a[mt][1], a[mt][2], a[mt][3]);
            #pragma unroll
            for (int i = 0; i < 4; i++)
                ldmx4(sB + (uint32_t)(((b_n + i * 16) * PADK + ks * 8 + b_kc) * 4),
                      bb[i][0], bb[i][1], bb[i][2], bb[i][3]);
            #pragma unroll
            for (int mt = 0; mt < 2; mt++)
                #pragma unroll
                for (int nt = 0; nt < 8; nt++)
                    mma_tf32(acc[mt][nt], a[mt],
                             bb[nt >> 1][(nt & 1) * 2], bb[nt >> 1][(nt & 1) * 2 + 1]);
        }
        __syncthreads();
    }

    // epilogue: c0,c1 = (row, 2c),(row,2c+1); c2,c3 = row+8
    int er = (lane >> 2), ec = (lane & 3) * 2;
    #pragma unroll
    for (int mt = 0; mt < 2; mt++) {
        size_t r0 = m0 + wm * 32 + mt * 16 + er;
        #pragma unroll
        for (int nt = 0; nt < 8; nt++) {
            int c0 = n0 + wn * 64 + nt * 8 + ec;
            float2 v0 = make_float2(acc[mt][nt][0], acc[mt][nt][1]);
            float2 v1 = make_float2(acc[mt][nt][2], acc[mt][nt][3]);
            if (act) {
                v0.x = rtf32(gelu_exact(v0.x)); v0.y = rtf32(gelu_exact(v0.y));
                v1.x = rtf32(gelu_exact(v1.x)); v1.y = rtf32(gelu_exact(v1.y));
            }
            *(float2*)(C + r0 * N + c0)       = v0;
            *(float2*)(C + (r0 + 8) * N + c0) = v1;
        }
    }
}

// ---------------- permutation: token -> shifted-window layout (tf32-round) --
__global__ __launch_bounds__(256) void perm_kernel(const float* __restrict__ src,
                                                   const float* __restrict__ tgt)
{
    int warp = (blockIdx.x * 256 + threadIdx.x) >> 5;
    int lane = threadIdx.x & 31;
    if (warp >= ROWS) return;
    int b   = warp >> 14;
    int wr  = warp & 16383;
    int win = wr >> 8;
    int pos = wr & 255;
    int ip = ((win >> 3) << 4) + (pos >> 4);
    int jp = ((win & 7) << 4) + (pos & 15);
    int i = (ip + 8) & 127;
    int j = (jp + 8) & 127;
    size_t srow = ((size_t)b * LTOK + (size_t)i * WWID + j) * CC;
    size_t drow = (size_t)warp * CC;
    float4 s4 = ((const float4*)(src + srow))[lane];
    float4 t4 = ((const float4*)(tgt + srow))[lane];
    s4.x = rtf32(s4.x); s4.y = rtf32(s4.y); s4.z = rtf32(s4.z); s4.w = rtf32(s4.w);
    t4.x = rtf32(t4.x); t4.y = rtf32(t4.y); t4.z = rtf32(t4.z); t4.w = rtf32(t4.w);
    ((float4*)(g_Sg + drow))[lane] = s4;
    ((float4*)(g_Tg + drow))[lane] = t4;
}

// ---------------- windowed attention (fp32 SIMT) ----------------------------
#define SD 257
#define ATTN_SMEM_FLOATS (128*SD + 64*128 + 64*128 + 256)
#define ATTN_SMEM_BYTES  (ATTN_SMEM_FLOATS*4)

__device__ __forceinline__ int region3(int x) { return (x < 112) ? 0 : ((x < 120) ? 1 : 2); }

__global__ __launch_bounds__(256) void attn_kernel()
{
    extern __shared__ float sm[];
    float* Ssh = sm;
    float* Kt  = sm + 128 * SD;
    float* Vt  = Kt + 64 * 128;
    float* ids = Vt + 64 * 128;

    int t    = threadIdx.x;
    int wb   = blockIdx.x >> 1;
    int half = blockIdx.x & 1;
    int row  = t >> 1;
    int part = t & 1;
    int qrow = half * 128 + row;

    int win = wb & 63;
    int wr = win >> 3, wc = win & 7;
    {
        int pr = t >> 4, pc = t & 15;
        ids[t] = (float)(region3(wr * 16 + pr) * 3 + region3(wc * 16 + pc));
    }
    float idq = (float)(region3(wr * 16 + (qrow >> 4)) * 3 + region3(wc * 16 + (qrow & 15)));

    size_t base = (size_t)wb * WSZ * CC;
    float4 qv[16];
    {
        const float* qp = g_QW + base + (size_t)qrow * CC + part * 4;
        #pragma unroll
        for (int g = 0; g < 16; g++) qv[g] = *(const float4*)(qp + g * 8);
    }

    float mloc = -1e30f;
    __syncthreads();

    for (int kt4 = 0; kt4 < 4; kt4++) {
        const float4* kg = (const float4*)(g_KW + base + (size_t)kt4 * 64 * CC);
        #pragma unroll
        for (int w = 0; w < 8; w++) ((float4*)Kt)[t + w * 256] = kg[t + w * 256];
        __syncthreads();
        #pragma unroll 2
        for (int j = 0; j < 64; j++) {
            const float* kp = Kt + j * CC + part * 4;
            float sp = 0.f;
            #pragma unroll
            for (int g = 0; g < 16; g++) {
                float4 kv = *(const float4*)(kp + g * 8);
                sp += qv[g].x * kv.x + qv[g].y * kv.y + qv[g].z * kv.z + qv[g].w * kv.w;
            }
            float s = sp + __shfl_xor_sync(0xffffffffu, sp, 1);
            int kj = kt4 * 64 + j;
            s = s * 0.08838834764831845f + ((idq != ids[kj]) ? -100.0f : 0.0f);
            if (part == 0) Ssh[row * SD + kj] = s;
            mloc = fmaxf(mloc, s);
        }
        __syncthreads();
    }

    float sum = 0.f;
    {
        float* sr = Ssh + row * SD + part * 128;
        #pragma unroll 4
        for (int jj = 0; jj < 128; jj++) {
            float p = __expf(sr[jj] - mloc);
            sr[jj] = p;
            sum += p;
        }
    }
    sum += __shfl_xor_sync(0xffffffffu, sum, 1);
    float inv = 1.0f / sum;
    __syncthreads();

    float4 acc[16];
    #pragma unroll
    for (int g = 0; g < 16; g++) acc[g] = make_float4(0.f, 0.f, 0.f, 0.f);

    for (int kt4 = 0; kt4 < 4; kt4++) {
        const float4* vg = (const float4*)(g_VW + base + (size_t)kt4 * 64 * CC);
        #pragma unroll
        for (int w = 0; w < 8; w++) ((float4*)Vt)[t + w * 256] = vg[t + w * 256];
        __syncthreads();
        #pragma unroll 2
        for (int j = 0; j < 64; j++) {
            float p = Ssh[row * SD + kt4 * 64 + j];
            const float* vp = Vt + j * CC + part * 4;
            #pragma unroll
            for (int g = 0; g < 16; g++) {
                float4 v = *(const float4*)(vp + g * 8);
                acc[g].x += p * v.x; acc[g].y += p * v.y;
                acc[g].z += p * v.z; acc[g].w += p * v.w;
            }
        }
        __syncthreads();
    }

    // attention output feeds the Wm tf32 gemm: round to tf32 here
    float* op = g_ATT + base + (size_t)qrow * CC + part * 4;
    #pragma unroll
    for (int g = 0; g < 16; g++) {
        float4 r = acc[g];
        r.x = rtf32(r.x * inv); r.y = rtf32(r.y * inv);
        r.z = rtf32(r.z * inv); r.w = rtf32(r.w * inv);
        *(float4*)(op + g * 8) = r;
    }
}

// ---------------- LN(msg) + un-shift gather + concat (tf32-round) ------------
__global__ __launch_bounds__(256) void ln_concat_kernel(const float* __restrict__ src,
                                                        const float* __restrict__ g1,
                                                        const float* __restrict__ b1)
{
    int warp = (blockIdx.x * 256 + threadIdx.x) >> 5;
    int lane = threadIdx.x & 31;
    if (warp >= ROWS) return;
    int b   = warp >> 14;
    int tok = warp & 16383;
    int i = tok >> 7, j = tok & 127;
    int ip = (i + 120) & 127;
    int jp = (j + 120) & 127;
    int win = ((ip >> 4) << 3) + (jp >> 4);
    int pos = ((ip & 15) << 4) + (jp & 15);
    size_t mrow = ((size_t)b * NWIN + win) * WSZ + pos;

    float4 mv = ((const float4*)(g_MSG + mrow * CC))[lane];
    float s  = mv.x + mv.y + mv.z + mv.w;
    float ss = mv.x * mv.x + mv.y * mv.y + mv.z * mv.z + mv.w * mv.w;
    #pragma unroll
    for (int o = 16; o > 0; o >>= 1) {
        s  += __shfl_xor_sync(0xffffffffu, s,  o);
        ss += __shfl_xor_sync(0xffffffffu, ss, o);
    }
    float mean = s * (1.0f / 128.0f);
    float var  = ss * (1.0f / 128.0f) - mean * mean;
    float r = rsqrtf(var + 1e-5f);
    float4 gv = ((const float4*)g1)[lane];
    float4 bv = ((const float4*)b1)[lane];
    float4 o4;
    o4.x = rtf32((mv.x - mean) * r * gv.x + bv.x);
    o4.y = rtf32((mv.y - mean) * r * gv.y + bv.y);
    o4.z = rtf32((mv.z - mean) * r * gv.z + bv.z);
    o4.w = rtf32((mv.w - mean) * r * gv.w + bv.w);

    float4 sv = ((const float4*)(src + (size_t)warp * CC))[lane];
    sv.x = rtf32(sv.x); sv.y = rtf32(sv.y); sv.z = rtf32(sv.z); sv.w = rtf32(sv.w);

    size_t frow = (size_t)warp * (2 * CC);
    ((float4*)(g_FIN + frow + CC))[lane] = o4;
    ((float4*)(g_FIN + frow))[lane] = sv;
}

// ---------------- final LN + residual ---------------------------------------
__global__ __launch_bounds__(256) void ln_res_kernel(const float* __restrict__ src,
                                                     const float* __restrict__ g2,
                                                     const float* __restrict__ b2,
                                                     float* __restrict__ out)
{
    int warp = (blockIdx.x * 256 + threadIdx.x) >> 5;
    int lane = threadIdx.x & 31;
    if (warp >= ROWS) return;

    float4 mv = ((const float4*)(g_MSG2 + (size_t)warp * CC))[lane];
    float s  = mv.x + mv.y + mv.z + mv.w;
    float ss = mv.x * mv.x + mv.y * mv.y + mv.z * mv.z + mv.w * mv.w;
    #pragma unroll
    for (int o = 16; o > 0; o >>= 1) {
        s  += __shfl_xor_sync(0xffffffffu, s,  o);
        ss += __shfl_xor_sync(0xffffffffu, ss, o);
    }
    float mean = s * (1.0f / 128.0f);
    float var  = ss * (1.0f / 128.0f) - mean * mean;
    float r = rsqrtf(var + 1e-5f);
    float4 gv = ((const float4*)g2)[lane];
    float4 bv = ((const float4*)b2)[lane];
    float4 sv = ((const float4*)(src + (size_t)warp * CC))[lane];
    float4 o4;
    o4.x = sv.x + (mv.x - mean) * r * gv.x + bv.x;
    o4.y = sv.y + (mv.y - mean) * r * gv.y + bv.y;
    o4.z = sv.z + (mv.z - mean) * r * gv.z + bv.z;
    o4.w = sv.w + (mv.w - mean) * r * gv.w + bv.w;
    ((float4*)(out + (size_t)warp * CC))[lane] = o4;
}

// ---------------- host launcher ---------------------------------------------
extern "C" void kernel_launch(void* const* d_in, const int* in_sizes, int n_in,
                              void* d_out, int out_size)
{
    const float* src = (const float*)d_in[0];
    const float* tgt = (const float*)d_in[1];
    const float* Wq  = (const float*)d_in[2];
    const float* Wk  = (const float*)d_in[3];
    const float* Wv  = (const float*)d_in[4];
    const float* Wm  = (const float*)d_in[5];
    const float* g1  = (const float*)d_in[6];
    const float* b1  = (const float*)d_in[7];
    const float* W1  = (const float*)d_in[8];
    const float* W2  = (const float*)d_in[9];
    const float* g2  = (const float*)d_in[10];
    const float* b2  = (const float*)d_in[11];

    float *Sg, *Tg, *QW, *KW, *VW, *ATT, *MSG, *FIN, *HIDp, *MSG2;
    float *WqT, *WkT, *WvT, *WmT, *W1T, *W2T;
    cudaGetSymbolAddress((void**)&Sg,   g_Sg);
    cudaGetSymbolAddress((void**)&Tg,   g_Tg);
    cudaGetSymbolAddress((void**)&QW,   g_QW);
    cudaGetSymbolAddress((void**)&KW,   g_KW);
    cudaGetSymbolAddress((void**)&VW,   g_VW);
    cudaGetSymbolAddress((void**)&ATT,  g_ATT);
    cudaGetSymbolAddress((void**)&MSG,  g_MSG);
    cudaGetSymbolAddress((void**)&FIN,  g_FIN);
    cudaGetSymbolAddress((void**)&HIDp, g_HID);
    cudaGetSymbolAddress((void**)&MSG2, g_MSG2);
    cudaGetSymbolAddress((void**)&WqT,  g_WqT);
    cudaGetSymbolAddress((void**)&WkT,  g_WkT);
    cudaGetSymbolAddress((void**)&WvT,  g_WvT);
    cudaGetSymbolAddress((void**)&WmT,  g_WmT);
    cudaGetSymbolAddress((void**)&W1T,  g_W1T);
    cudaGetSymbolAddress((void**)&W2T,  g_W2T);

    cudaFuncSetAttribute(attn_kernel, cudaFuncAttributeMaxDynamicSharedMemorySize,
                         ATTN_SMEM_BYTES);
    cudaFuncSetAttribute(gemm_tc, cudaFuncAttributeMaxDynamicSharedMemorySize,
                         GSM_TOTAL);

    // 0) transpose weights to [N, K] (rounded to tf32)
    transpose32<<<dim3(4, 4),  dim3(32, 8)>>>(Wq, WqT, CC, CC);
    transpose32<<<dim3(4, 4),  dim3(32, 8)>>>(Wk, WkT, CC, CC);
    transpose32<<<dim3(4, 4),  dim3(32, 8)>>>(Wv, WvT, CC, CC);
    transpose32<<<dim3(4, 4),  dim3(32, 8)>>>(Wm, WmT, CC, CC);
    transpose32<<<dim3(32, 8), dim3(32, 8)>>>(W1, W1T, 2 * CC, HIDN);
    transpose32<<<dim3(4, 32), dim3(32, 8)>>>(W2, W2T, HIDN, CC);

    // 1) shift + window partition (rounded to tf32)
    perm_kernel<<<4096, 256>>>(src, tgt);

    // 2) Q/K/V projections (tf32 mma.sync)
    gemm_tc<<<dim3(1, 256), 256, GSM_TOTAL>>>(Sg, WqT, QW, ROWS, 128, 128, 0);
    gemm_tc<<<dim3(1, 256), 256, GSM_TOTAL>>>(Tg, WkT, KW, ROWS, 128, 128, 0);
    gemm_tc<<<dim3(1, 256), 256, GSM_TOTAL>>>(Tg, WvT, VW, ROWS, 128, 128, 0);

    // 3) shifted-window attention
    attn_kernel<<<2 * BB * NWIN, 256, ATTN_SMEM_BYTES>>>();

    // 4) message projection
    gemm_tc<<<dim3(1, 256), 256, GSM_TOTAL>>>(ATT, WmT, MSG, ROWS, 128, 128, 0);

    // 5) LN(msg) + un-shift + concat
    ln_concat_kernel<<<4096, 256>>>(src, g1, b1);

    // 6) FFN
    gemm_tc<<<dim3(8, 256), 256, GSM_TOTAL>>>(FIN, W1T, HIDp, ROWS, HIDN, 2 * CC, 1);
    gemm_tc<<<dim3(1, 256), 256, GSM_TOTAL>>>(HIDp, W2T, MSG2, ROWS, 128, HIDN, 0);

    // 7) final LN + residual
    ln_res_kernel<<<4096, 256>>>(src, g2, b2, (float*)d_out);
}

// round 4
// speedup vs baseline: 2.8885x; 1.3032x over previous
#include <cuda_runtime.h>
#include <math.h>
#include <stdint.h>

// Problem constants
#define BB   2
#define HH   128
#define WWID 128
#define CC   128
#define NWIN 64
#define WSZ  256
#define LTOK (HH*WWID)     // 16384
#define ROWS (BB*LTOK)     // 32768
#define HIDN 1024

// ---------------- scratch ---------------------------------------------------
__device__ float g_Sg[ROWS*CC];
__device__ float g_Tg[ROWS*CC];
__device__ float g_QW[ROWS*CC];
__device__ float g_KW[ROWS*CC];
__device__ float g_VW[ROWS*CC];
__device__ float g_VWt[ROWS*CC];     // per-window transposed V: [wb][dim][key]
__device__ float g_ATT[ROWS*CC];
__device__ float g_MSG[ROWS*CC];
__device__ float g_FIN[(size_t)ROWS*2*CC];
__device__ float g_HID[(size_t)ROWS*HIDN];
__device__ float g_MSG2[ROWS*CC];
// transposed weights [N, K]
__device__ float g_WqT[CC*CC];
__device__ float g_WkT[CC*CC];
__device__ float g_WvT[CC*CC];
__device__ float g_WmT[CC*CC];
__device__ float g_W1T[HIDN*2*CC];
__device__ float g_W2T[CC*HIDN];

// ---------------- helpers ---------------------------------------------------
__device__ __forceinline__ float rtf32(float x) {
    float y; asm("cvt.rna.tf32.f32 %0, %1;" : "=f"(y) : "f"(x)); return y;
}
__device__ __forceinline__ float gelu_exact(float x) {
    return 0.5f * x * (1.0f + erff(x * 0.70710678118654752f));
}
__device__ __forceinline__ uint32_t smem_u32(const void* p) {
    uint32_t a;
    asm("{ .reg .u64 t; cvta.to.shared.u64 t, %1; cvt.u32.u64 %0, t; }" : "=r"(a) : "l"(p));
    return a;
}
__device__ __forceinline__ void cpasync16(uint32_t dst, const float* src) {
    asm volatile("cp.async.cg.shared.global [%0], [%1], 16;" :: "r"(dst), "l"(src));
}
__device__ __forceinline__ void ldmx4(uint32_t addr, uint32_t& d0, uint32_t& d1,
                                      uint32_t& d2, uint32_t& d3) {
    asm volatile("ldmatrix.sync.aligned.m8n8.x4.shared.b16 {%0,%1,%2,%3}, [%4];"
                 : "=r"(d0), "=r"(d1), "=r"(d2), "=r"(d3) : "r"(addr));
}
__device__ __forceinline__ void mma_tf32(float* c, const uint32_t* a, uint32_t b0, uint32_t b1) {
    asm volatile("mma.sync.aligned.m16n8k8.row.col.f32.tf32.tf32.f32 "
                 "{%0,%1,%2,%3}, {%4,%5,%6,%7}, {%8,%9}, {%0,%1,%2,%3};"
                 : "+f"(c[0]), "+f"(c[1]), "+f"(c[2]), "+f"(c[3])
                 : "r"(a[0]), "r"(a[1]), "r"(a[2]), "r"(a[3]), "r"(b0), "r"(b1));
}

// ---------------- weight transpose (round to tf32) --------------------------
__global__ __launch_bounds__(256) void transpose32(const float* __restrict__ in,
                                                   float* __restrict__ out, int R, int C)
{
    __shared__ float t[32][33];
    int bx = blockIdx.x * 32, by = blockIdx.y * 32;
    int x = bx + threadIdx.x;
    #pragma unroll
    for (int i = 0; i < 32; i += 8)
        t[threadIdx.y + i][threadIdx.x] = in[(size_t)(by + threadIdx.y + i) * C + x];
    __syncthreads();
    int x2 = by + threadIdx.x;
    #pragma unroll
    for (int i = 0; i < 32; i += 8)
        out[(size_t)(bx + threadIdx.y + i) * R + x2] = rtf32(t[threadIdx.x][threadIdx.y + i]);
}

// ---------------- per-window V transpose: g_VW -> g_VWt[wb][dim][key] -------
__global__ __launch_bounds__(256) void vtrans_kernel()
{
    __shared__ float t[32][33];
    int wb = blockIdx.z;
    int d0 = blockIdx.x * 32, k0 = blockIdx.y * 32;
    int tx = threadIdx.x, ty = threadIdx.y;
    const float* src = g_VW + (size_t)wb * 32768;
    #pragma unroll
    for (int i = 0; i < 32; i += 8)
        t[ty + i][tx] = src[(size_t)(k0 + ty + i) * 128 + d0 + tx];
    __syncthreads();
    float* dst = g_VWt + (size_t)wb * 32768;
    #pragma unroll
    for (int i = 0; i < 32; i += 8)
        dst[(size_t)(d0 + ty + i) * 256 + k0 + tx] = rtf32(t[tx][ty + i]);
}

// ---------------- tf32 mma.sync GEMM: C[M,N] = A[M,K] @ Bt[N,K]^T -----------
#define PADK 36
#define TILE_BYTES (128*PADK*4)     // 18432
#define SA0 0
#define SA1 TILE_BYTES
#define SB0 (2*TILE_BYTES)
#define SB1 (3*TILE_BYTES)
#define GSM_TOTAL (4*TILE_BYTES)    // 73728

__device__ __forceinline__ void load_tile(uint32_t sbase, const float* __restrict__ G,
                                          int ld, size_t row0, int col0, int tid)
{
    int r = tid >> 3, c4 = (tid & 7) * 4;
    #pragma unroll
    for (int i = 0; i < 4; i++) {
        int row = i * 32 + r;
        cpasync16(sbase + (uint32_t)((row * PADK + c4) * 4),
                  G + (row0 + row) * (size_t)ld + col0 + c4);
    }
}

__global__ __launch_bounds__(256) void gemm_tc(const float* __restrict__ A,
                                               const float* __restrict__ Bt,
                                               float* __restrict__ C,
                                               int M, int N, int K, int act)
{
    extern __shared__ char smem[];
    uint32_t sb = smem_u32(smem);
    int tid = threadIdx.x, wid = tid >> 5, lane = tid & 31;
    int wm = wid & 3, wn = wid >> 2;
    size_t m0 = (size_t)blockIdx.y * 128;
    int n0 = blockIdx.x * 128;
    const int nk = K >> 5;

    float acc[2][8][4];
    #pragma unroll
    for (int mt = 0; mt < 2; mt++)
        #pragma unroll
        for (int nt = 0; nt < 8; nt++)
            #pragma unroll
            for (int i = 0; i < 4; i++) acc[mt][nt][i] = 0.f;

    int mat = lane >> 3, mr = lane & 7;
    int a_row = wm * 32 + (mat & 1) * 8 + mr;
    int a_kc  = (mat >> 1) * 4;
    int b_n  = wn * 64 + (mat >> 1) * 8 + mr;
    int b_kc = (mat & 1) * 4;

    load_tile(sb + SA0, A, K, m0, 0, tid);
    load_tile(sb + SB0, Bt, K, (size_t)n0, 0, tid);
    asm volatile("cp.async.commit_group;");

    for (int kt = 0; kt < nk; kt++) {
        int b = kt & 1;
        if (kt + 1 < nk) {
            load_tile(sb + (b ? SA0 : SA1), A, K, m0, (kt + 1) * 32, tid);
            load_tile(sb + (b ? SB0 : SB1), Bt, K, (size_t)n0, (kt + 1) * 32, tid);
            asm volatile("cp.async.commit_group;");
            asm volatile("cp.async.wait_group 1;");
        } else {
            asm volatile("cp.async.wait_group 0;");
        }
        __syncthreads();

        uint32_t sA = sb + (b ? SA1 : SA0);
        uint32_t sB = sb + (b ? SB1 : SB0);
        #pragma unroll
        for (int ks = 0; ks < 4; ks++) {
            uint32_t a[2][4], bb[4][4];
            #pragma unroll
            for (int mt = 0; mt < 2; mt++)
                ldmx4(sA + (uint32_t)(((a_row + mt * 16) * PADK + ks * 8 + a_kc) * 4),
                      a[mt][0], a[mt][1], a[mt][2], a[mt][3]);
            #pragma unroll
            for (int i = 0; i < 4; i++)
                ldmx4(sB + (uint32_t)(((b_n + i * 16) * PADK + ks * 8 + b_kc) * 4),
                      bb[i][0], bb[i][1], bb[i][2], bb[i][3]);
            #pragma unroll
            for (int mt = 0; mt < 2; mt++)
                #pragma unroll
                for (int nt = 0; nt < 8; nt++)
                    mma_tf32(acc[mt][nt], a[mt],
                             bb[nt >> 1][(nt & 1) * 2], bb[nt >> 1][(nt & 1) * 2 + 1]);
        }
        __syncthreads();
    }

    int er = (lane >> 2), ec = (lane & 3) * 2;
    #pragma unroll
    for (int mt = 0; mt < 2; mt++) {
        size_t r0 = m0 + wm * 32 + mt * 16 + er;
        #pragma unroll
        for (int nt = 0; nt < 8; nt++) {
            int c0 = n0 + wn * 64 + nt * 8 + ec;
            float2 v0 = make_float2(acc[mt][nt][0], acc[mt][nt][1]);
            float2 v1 = make_float2(acc[mt][nt][2], acc[mt][nt][3]);
            if (act) {
                v0.x = rtf32(gelu_exact(v0.x)); v0.y = rtf32(gelu_exact(v0.y));
                v1.x = rtf32(gelu_exact(v1.x)); v1.y = rtf32(gelu_exact(v1.y));
            }
            *(float2*)(C + r0 * N + c0)       = v0;
            *(float2*)(C + (r0 + 8) * N + c0) = v1;
        }
    }
}

// ---------------- permutation: token -> shifted-window layout (tf32-round) --
__global__ __launch_bounds__(256) void perm_kernel(const float* __restrict__ src,
                                                   const float* __restrict__ tgt)
{
    int warp = (blockIdx.x * 256 + threadIdx.x) >> 5;
    int lane = threadIdx.x & 31;
    if (warp >= ROWS) return;
    int b   = warp >> 14;
    int wr  = warp & 16383;
    int win = wr >> 8;
    int pos = wr & 255;
    int ip = ((win >> 3) << 4) + (pos >> 4);
    int jp = ((win & 7) << 4) + (pos & 15);
    int i = (ip + 8) & 127;
    int j = (jp + 8) & 127;
    size_t srow = ((size_t)b * LTOK + (size_t)i * WWID + j) * CC;
    size_t drow = (size_t)warp * CC;
    float4 s4 = ((const float4*)(src + srow))[lane];
    float4 t4 = ((const float4*)(tgt + srow))[lane];
    s4.x = rtf32(s4.x); s4.y = rtf32(s4.y); s4.z = rtf32(s4.z); s4.w = rtf32(s4.w);
    t4.x = rtf32(t4.x); t4.y = rtf32(t4.y); t4.z = rtf32(t4.z); t4.w = rtf32(t4.w);
    ((float4*)(g_Sg + drow))[lane] = s4;
    ((float4*)(g_Tg + drow))[lane] = t4;
}

// ---------------- windowed attention via tf32 mma.sync ----------------------
// CTA = quarter window (64 q rows), 256 threads / 8 warps.
// smem floats: Qs [4][64][36] | Ss [64][260] | Ks/Vts [64*144] | Inv [64]
#define ATQ 0
#define ATS (4*64*36)                 // 9216
#define ATK (ATS + 64*260)            // 25856
#define ATI (ATK + 4*64*36)           // 35072
#define AT_SMEM_BYTES ((ATI + 64)*4)  // 140544

__device__ __forceinline__ int region3(int x) { return (x < 112) ? 0 : ((x < 120) ? 1 : 2); }
__device__ __forceinline__ int posid(int p, int wr, int wc) {
    return region3(wr * 16 + (p >> 4)) * 3 + region3(wc * 16 + (p & 15));
}

__global__ __launch_bounds__(256) void attn_mma()
{
    extern __shared__ float sm[];
    uint32_t sB = smem_u32(sm);

    const int tid = threadIdx.x;
    const int lane = tid & 31, w = tid >> 5;
    const int wb = blockIdx.x >> 2, quar = blockIdx.x & 3;
    const int q0 = quar * 64;
    const int win = wb & 63, wr = win >> 3, wc = win & 7;
    const size_t wbase = (size_t)wb * 256 * 128;

    const int wm = w & 3, wn = w >> 2;
    const int mat = lane >> 3, mr = lane & 7;
    const int a_row = wm * 16 + (mat & 1) * 8 + mr;   // local q row for A frags
    const int a_kc  = (mat >> 1) * 4;
    const int bn_off = (mat >> 1) * 8 + mr;
    const int b_kc   = (mat & 1) * 4;
    const int er = lane >> 2, ec = (lane & 3) * 2;

    // ---- load Q (64 rows), rtf32, chunked [c][row][36] ----
    {
        int r = tid >> 2, f = tid & 3;
        const float* qp = g_QW + wbase + (size_t)(q0 + r) * 128;
        #pragma unroll
        for (int i2 = 0; i2 < 8; i2++) {
            int d4 = f + 4 * i2;
            float4 v = *(const float4*)(qp + d4 * 4);
            v.x = rtf32(v.x); v.y = rtf32(v.y); v.z = rtf32(v.z); v.w = rtf32(v.w);
            *(float4*)(sm + ATQ + ((d4 >> 3) * 64 + r) * 36 + (d4 & 7) * 4) = v;
        }
    }

    const int rq = wm * 16 + er;     // local q row of accum c0/c1 (c2/c3 -> +8)
    const int idq0 = posid(q0 + rq, wr, wc);
    const int idq1 = posid(q0 + rq + 8, wr, wc);
    const float SC = 0.08838834764831845f;

    // ---- phase A: S = Q @ K^T (K natural layout is the B operand) ----
    for (int kb = 0; kb < 4; kb++) {
        __syncthreads();
        {   // load K block rows kb*64..+63
            int r = tid >> 2, f = tid & 3;
            const float* kp = g_KW + wbase + (size_t)(kb * 64 + r) * 128;
            #pragma unroll
            for (int i2 = 0; i2 < 8; i2++) {
                int d4 = f + 4 * i2;
                float4 v = *(const float4*)(kp + d4 * 4);
                v.x = rtf32(v.x); v.y = rtf32(v.y); v.z = rtf32(v.z); v.w = rtf32(v.w);
                *(float4*)(sm + ATK + ((d4 >> 3) * 64 + r) * 36 + (d4 & 7) * 4) = v;
            }
        }
        __syncthreads();

        float sacc[4][4];
        #pragma unroll
        for (int nt = 0; nt < 4; nt++)
            #pragma unroll
            for (int i = 0; i < 4; i++) sacc[nt][i] = 0.f;

        #pragma unroll
        for (int c = 0; c < 4; c++)
            #pragma unroll
            for (int ks = 0; ks < 4; ks++) {
                uint32_t a[4], bbf[2][4];
                ldmx4(sB + (uint32_t)((ATQ + (c * 64 + a_row) * 36 + ks * 8 + a_kc) * 4),
                      a[0], a[1], a[2], a[3]);
                #pragma unroll
                for (int h = 0; h < 2; h++)
                    ldmx4(sB + (uint32_t)((ATK + (c * 64 + wn * 32 + h * 16 + bn_off) * 36 + ks * 8 + b_kc) * 4),
                          bbf[h][0], bbf[h][1], bbf[h][2], bbf[h][3]);
                #pragma unroll
                for (int nt = 0; nt < 4; nt++)
                    mma_tf32(sacc[nt], a, bbf[nt >> 1][(nt & 1) * 2], bbf[nt >> 1][(nt & 1) * 2 + 1]);
            }

        // write S with scale + mask
        #pragma unroll
        for (int nt = 0; nt < 4; nt++) {
            int key = kb * 64 + wn * 32 + nt * 8 + ec;
            int idk0 = posid(key, wr, wc), idk1 = posid(key + 1, wr, wc);
            float2 v0, v1;
            v0.x = sacc[nt][0] * SC + ((idq0 == idk0) ? 0.f : -100.f);
            v0.y = sacc[nt][1] * SC + ((idq0 == idk1) ? 0.f : -100.f);
            v1.x = sacc[nt][2] * SC + ((idq1 == idk0) ? 0.f : -100.f);
            v1.y = sacc[nt][3] * SC + ((idq1 == idk1) ? 0.f : -100.f);
            *(float2*)(sm + ATS + rq * 260 + key)       = v0;
            *(float2*)(sm + ATS + (rq + 8) * 260 + key) = v1;
        }
    }
    __syncthreads();

    // ---- softmax: 4 threads per row, stride-4 columns (conflict-free) ----
    {
        int row = tid >> 2, sub = tid & 3;
        float* sr = sm + ATS + row * 260 + sub;
        float mx = -1e30f;
        #pragma unroll 8
        for (int i = 0; i < 64; i++) mx = fmaxf(mx, sr[i * 4]);
        mx = fmaxf(mx, __shfl_xor_sync(0xffffffffu, mx, 1));
        mx = fmaxf(mx, __shfl_xor_sync(0xffffffffu, mx, 2));
        float s = 0.f;
        #pragma unroll 8
        for (int i = 0; i < 64; i++) {
            float p = __expf(sr[i * 4] - mx);
            sr[i * 4] = rtf32(p);
            s += p;
        }
        s += __shfl_xor_sync(0xffffffffu, s, 1);
        s += __shfl_xor_sync(0xffffffffu, s, 2);
        if ((tid & 3) == 0) sm[ATI + row] = 1.0f / s;
    }

    // ---- phase B: O = P @ V (B operand from pre-transposed g_VWt) ----
    float oacc[8][4];
    #pragma unroll
    for (int nt = 0; nt < 8; nt++)
        #pragma unroll
        for (int i = 0; i < 4; i++) oacc[nt][i] = 0.f;

    for (int kb = 0; kb < 4; kb++) {
        __syncthreads();
        {   // load Vt block: [dim 0..127][keys kb*64..+63] chunked [c2][dim][36]
            int dim = tid >> 1, kf = tid & 1;
            const float* vp = g_VWt + (size_t)wb * 32768 + (size_t)dim * 256 + kb * 64;
            #pragma unroll
            for (int i2 = 0; i2 < 8; i2++) {
                int k4 = kf + 2 * i2;
                float4 v = *(const float4*)(vp + k4 * 4);
                *(float4*)(sm + ATK + ((k4 >> 3) * 128 + dim) * 36 + (k4 & 7) * 4) = v;
            }
        }
        __syncthreads();

        #pragma unroll
        for (int c2 = 0; c2 < 2; c2++)
            #pragma unroll
            for (int ks = 0; ks < 4; ks++) {
                uint32_t a[4], bv[4][4];
                ldmx4(sB + (uint32_t)((ATS + a_row * 260 + kb * 64 + c2 * 32 + ks * 8 + a_kc) * 4),
                      a[0], a[1], a[2], a[3]);
                #pragma unroll
                for (int h = 0; h < 4; h++)
                    ldmx4(sB + (uint32_t)((ATK + (c2 * 128 + wn * 64 + h * 16 + bn_off) * 36 + ks * 8 + b_kc) * 4),
                          bv[h][0], bv[h][1], bv[h][2], bv[h][3]);
                #pragma unroll
                for (int nt = 0; nt < 8; nt++)
                    mma_tf32(oacc[nt], a, bv[nt >> 1][(nt & 1) * 2], bv[nt >> 1][(nt & 1) * 2 + 1]);
            }
    }

    // ---- epilogue: scale by 1/sum, rtf32 (feeds Wm gemm), store ----
    {
        float i0 = sm[ATI + rq], i1 = sm[ATI + rq + 8];
        float* op = g_ATT + wbase + (size_t)(q0 + rq) * 128;
        #pragma unroll
        for (int nt = 0; nt < 8; nt++) {
            int dim = wn * 64 + nt * 8 + ec;
            float2 v0, v1;
            v0.x = rtf32(oacc[nt][0] * i0); v0.y = rtf32(oacc[nt][1] * i0);
            v1.x = rtf32(oacc[nt][2] * i1); v1.y = rtf32(oacc[nt][3] * i1);
            *(float2*)(op + dim)            = v0;
            *(float2*)(op + 8 * 128 + dim)  = v1;
        }
    }
}

// ---------------- LN(msg) + un-shift gather + concat (tf32-round) ------------
__global__ __launch_bounds__(256) void ln_concat_kernel(const float* __restrict__ src,
                                                        const float* __restrict__ g1,
                                                        const float* __restrict__ b1)
{
    int warp = (blockIdx.x * 256 + threadIdx.x) >> 5;
    int lane = threadIdx.x & 31;
    if (warp >= ROWS) return;
    int b   = warp >> 14;
    int tok = warp & 16383;
    int i = tok >> 7, j = tok & 127;
    int ip = (i + 120) & 127;
    int jp = (j + 120) & 127;
    int win = ((ip >> 4) << 3) + (jp >> 4);
    int pos = ((ip & 15) << 4) + (jp & 15);
    size_t mrow = ((size_t)b * NWIN + win) * WSZ + pos;

    float4 mv = ((const float4*)(g_MSG + mrow * CC))[lane];
    float s  = mv.x + mv.y + mv.z + mv.w;
    float ss = mv.x * mv.x + mv.y * mv.y + mv.z * mv.z + mv.w * mv.w;
    #pragma unroll
    for (int o = 16; o > 0; o >>= 1) {
        s  += __shfl_xor_sync(0xffffffffu, s,  o);
        ss += __shfl_xor_sync(0xffffffffu, ss, o);
    }
    float mean = s * (1.0f / 128.0f);
    float var  = ss * (1.0f / 128.0f) - mean * mean;
    float r = rsqrtf(var + 1e-5f);
    float4 gv = ((const float4*)g1)[lane];
    float4 bv = ((const float4*)b1)[lane];
    float4 o4;
    o4.x = rtf32((mv.x - mean) * r * gv.x + bv.x);
    o4.y = rtf32((mv.y - mean) * r * gv.y + bv.y);
    o4.z = rtf32((mv.z - mean) * r * gv.z + bv.z);
    o4.w = rtf32((mv.w - mean) * r * gv.w + bv.w);

    float4 sv = ((const float4*)(src + (size_t)warp * CC))[lane];
    sv.x = rtf32(sv.x); sv.y = rtf32(sv.y); sv.z = rtf32(sv.z); sv.w = rtf32(sv.w);

    size_t frow = (size_t)warp * (2 * CC);
    ((float4*)(g_FIN + frow + CC))[lane] = o4;
    ((float4*)(g_FIN + frow))[lane] = sv;
}

// ---------------- final LN + residual ---------------------------------------
__global__ __launch_bounds__(256) void ln_res_kernel(const float* __restrict__ src,
                                                     const float* __restrict__ g2,
                                                     const float* __restrict__ b2,
                                                     float* __restrict__ out)
{
    int warp = (blockIdx.x * 256 + threadIdx.x) >> 5;
    int lane = threadIdx.x & 31;
    if (warp >= ROWS) return;

    float4 mv = ((const float4*)(g_MSG2 + (size_t)warp * CC))[lane];
    float s  = mv.x + mv.y + mv.z + mv.w;
    float ss = mv.x * mv.x + mv.y * mv.y + mv.z * mv.z + mv.w * mv.w;
    #pragma unroll
    for (int o = 16; o > 0; o >>= 1) {
        s  += __shfl_xor_sync(0xffffffffu, s,  o);
        ss += __shfl_xor_sync(0xffffffffu, ss, o);
    }
    float mean = s * (1.0f / 128.0f);
    float var  = ss * (1.0f / 128.0f) - mean * mean;
    float r = rsqrtf(var + 1e-5f);
    float4 gv = ((const float4*)g2)[lane];
    float4 bv = ((const float4*)b2)[lane];
    float4 sv = ((const float4*)(src + (size_t)warp * CC))[lane];
    float4 o4;
    o4.x = sv.x + (mv.x - mean) * r * gv.x + bv.x;
    o4.y = sv.y + (mv.y - mean) * r * gv.y + bv.y;
    o4.z = sv.z + (mv.z - mean) * r * gv.z + bv.z;
    o4.w = sv.w + (mv.w - mean) * r * gv.w + bv.w;
    ((float4*)(out + (size_t)warp * CC))[lane] = o4;
}

// ---------------- host launcher ---------------------------------------------
extern "C" void kernel_launch(void* const* d_in, const int* in_sizes, int n_in,
                              void* d_out, int out_size)
{
    const float* src = (const float*)d_in[0];
    const float* tgt = (const float*)d_in[1];
    const float* Wq  = (const float*)d_in[2];
    const float* Wk  = (const float*)d_in[3];
    const float* Wv  = (const float*)d_in[4];
    const float* Wm  = (const float*)d_in[5];
    const float* g1  = (const float*)d_in[6];
    const float* b1  = (const float*)d_in[7];
    const float* W1  = (const float*)d_in[8];
    const float* W2  = (const float*)d_in[9];
    const float* g2  = (const float*)d_in[10];
    const float* b2  = (const float*)d_in[11];

    float *Sg, *Tg, *QW, *KW, *VW, *ATT, *MSG, *FIN, *HIDp, *MSG2;
    float *WqT, *WkT, *WvT, *WmT, *W1T, *W2T;
    cudaGetSymbolAddress((void**)&Sg,   g_Sg);
    cudaGetSymbolAddress((void**)&Tg,   g_Tg);
    cudaGetSymbolAddress((void**)&QW,   g_QW);
    cudaGetSymbolAddress((void**)&KW,   g_KW);
    cudaGetSymbolAddress((void**)&VW,   g_VW);
    cudaGetSymbolAddress((void**)&ATT,  g_ATT);
    cudaGetSymbolAddress((void**)&MSG,  g_MSG);
    cudaGetSymbolAddress((void**)&FIN,  g_FIN);
    cudaGetSymbolAddress((void**)&HIDp, g_HID);
    cudaGetSymbolAddress((void**)&MSG2, g_MSG2);
    cudaGetSymbolAddress((void**)&WqT,  g_WqT);
    cudaGetSymbolAddress((void**)&WkT,  g_WkT);
    cudaGetSymbolAddress((void**)&WvT,  g_WvT);
    cudaGetSymbolAddress((void**)&WmT,  g_WmT);
    cudaGetSymbolAddress((void**)&W1T,  g_W1T);
    cudaGetSymbolAddress((void**)&W2T,  g_W2T);

    cudaFuncSetAttribute(gemm_tc, cudaFuncAttributeMaxDynamicSharedMemorySize, GSM_TOTAL);
    cudaFuncSetAttribute(attn_mma, cudaFuncAttributeMaxDynamicSharedMemorySize, AT_SMEM_BYTES);

    // 0) transpose weights to [N, K] (rounded to tf32)
    transpose32<<<dim3(4, 4),  dim3(32, 8)>>>(Wq, WqT, CC, CC);
    transpose32<<<dim3(4, 4),  dim3(32, 8)>>>(Wk, WkT, CC, CC);
    transpose32<<<dim3(4, 4),  dim3(32, 8)>>>(Wv, WvT, CC, CC);
    transpose32<<<dim3(4, 4),  dim3(32, 8)>>>(Wm, WmT, CC, CC);
    transpose32<<<dim3(32, 8), dim3(32, 8)>>>(W1, W1T, 2 * CC, HIDN);
    transpose32<<<dim3(4, 32), dim3(32, 8)>>>(W2, W2T, HIDN, CC);

    // 1) shift + window partition (rounded to tf32)
    perm_kernel<<<4096, 256>>>(src, tgt);

    // 2) Q/K/V projections (tf32 mma.sync)
    gemm_tc<<<dim3(1, 256), 256, GSM_TOTAL>>>(Sg, WqT, QW, ROWS, 128, 128, 0);
    gemm_tc<<<dim3(1, 256), 256, GSM_TOTAL>>>(Tg, WkT, KW, ROWS, 128, 128, 0);
    gemm_tc<<<dim3(1, 256), 256, GSM_TOTAL>>>(Tg, WvT, VW, ROWS, 128, 128, 0);

    // 2b) per-window V transpose (tf32-rounded) for attention's B operand
    vtrans_kernel<<<dim3(4, 8, 128), dim3(32, 8)>>>();

    // 3) shifted-window attention (tf32 mma.sync)
    attn_mma<<<4 * BB * NWIN, 256, AT_SMEM_BYTES>>>();

    // 4) message projection
    gemm_tc<<<dim3(1, 256), 256, GSM_TOTAL>>>(ATT, WmT, MSG, ROWS, 128, 128, 0);

    // 5) LN(msg) + un-shift + concat
    ln_concat_kernel<<<4096, 256>>>(src, g1, b1);

    // 6) FFN
    gemm_tc<<<dim3(8, 256), 256, GSM_TOTAL>>>(FIN, W1T, HIDp, ROWS, HIDN, 2 * CC, 1);
    gemm_tc<<<dim3(1, 256), 256, GSM_TOTAL>>>(HIDp, W2T, MSG2, ROWS, 128, HIDN, 0);

    // 7) final LN + residual
    ln_res_kernel<<<4096, 256>>>(src, g2, b2, (float*)d_out);
}

// round 5
// speedup vs baseline: 3.9637x; 1.3722x over previous
#include <cuda_runtime.h>
#include <cuda_fp16.h>
#include <math.h>
#include <stdint.h>

// Problem constants
#define BB   2
#define HH   128
#define WWID 128
#define CC   128
#define NWIN 64
#define WSZ  256
#define LTOK (HH*WWID)     // 16384
#define ROWS (BB*LTOK)     // 32768
#define HIDN 1024

// ---------------- scratch ---------------------------------------------------
__device__ __half g_Sg[ROWS*CC];
__device__ __half g_Tg[ROWS*CC];
__device__ __half g_QW[ROWS*CC];
__device__ __half g_KW[ROWS*CC];
__device__ __half g_VW[ROWS*CC];
__device__ __half g_VWt[ROWS*CC];          // per-window transposed V: [wb][dim][key]
__device__ __half g_ATT[ROWS*CC];
__device__ float  g_MSG[ROWS*CC];          // fp32 (feeds LayerNorm)
__device__ __half g_FIN[(size_t)ROWS*2*CC];
__device__ __half g_HID[(size_t)ROWS*HIDN];
__device__ float  g_MSG2[ROWS*CC];         // fp32 (feeds LayerNorm)
// transposed weights [N, K] in fp16
__device__ __half g_WqT[CC*CC];
__device__ __half g_WkT[CC*CC];
__device__ __half g_WvT[CC*CC];
__device__ __half g_WmT[CC*CC];
__device__ __half g_W1T[HIDN*2*CC];
__device__ __half g_W2T[CC*HIDN];

// ---------------- helpers ---------------------------------------------------
__device__ __forceinline__ float gelu_exact(float x) {
    return 0.5f * x * (1.0f + erff(x * 0.70710678118654752f));
}
__device__ __forceinline__ uint32_t smem_u32(const void* p) {
    uint32_t a;
    asm("{ .reg .u64 t; cvta.to.shared.u64 t, %1; cvt.u32.u64 %0, t; }" : "=r"(a) : "l"(p));
    return a;
}
__device__ __forceinline__ void cpasync16(uint32_t dst, const __half* src) {
    asm volatile("cp.async.cg.shared.global [%0], [%1], 16;" :: "r"(dst), "l"(src));
}
__device__ __forceinline__ void ldmx4(uint32_t addr, uint32_t& d0, uint32_t& d1,
                                      uint32_t& d2, uint32_t& d3) {
    asm volatile("ldmatrix.sync.aligned.m8n8.x4.shared.b16 {%0,%1,%2,%3}, [%4];"
                 : "=r"(d0), "=r"(d1), "=r"(d2), "=r"(d3) : "r"(addr));
}
__device__ __forceinline__ void mma_h(float* c, const uint32_t* a, uint32_t b0, uint32_t b1) {
    asm volatile("mma.sync.aligned.m16n8k16.row.col.f32.f16.f16.f32 "
                 "{%0,%1,%2,%3}, {%4,%5,%6,%7}, {%8,%9}, {%0,%1,%2,%3};"
                 : "+f"(c[0]), "+f"(c[1]), "+f"(c[2]), "+f"(c[3])
                 : "r"(a[0]), "r"(a[1]), "r"(a[2]), "r"(a[3]), "r"(b0), "r"(b1));
}

// ---------------- batched weight transpose: fp32 [R,C] -> fp16 [C,R] --------
__global__ __launch_bounds__(256) void transpose_all(const float* __restrict__ Wq,
                                                     const float* __restrict__ Wk,
                                                     const float* __restrict__ Wv,
                                                     const float* __restrict__ Wm,
                                                     const float* __restrict__ W1,
                                                     const float* __restrict__ W2)
{
    __shared__ float t[32][33];
    int id = blockIdx.x;
    const float* src; __half* dst; int R, C, bx, by;
    if (id < 64) {
        int wsel = id >> 4, tt = id & 15;
        bx = tt & 3; by = tt >> 2; R = 128; C = 128;
        src = (wsel == 0) ? Wq : (wsel == 1) ? Wk : (wsel == 2) ? Wv : Wm;
        dst = (wsel == 0) ? g_WqT : (wsel == 1) ? g_WkT : (wsel == 2) ? g_WvT : g_WmT;
    } else if (id < 320) {
        int tt = id - 64; bx = tt & 31; by = tt >> 5; R = 256; C = 1024;
        src = W1; dst = g_W1T;
    } else {
        int tt = id - 320; bx = tt & 3; by = tt >> 2; R = 1024; C = 128;
        src = W2; dst = g_W2T;
    }
    int tx = threadIdx.x, ty = threadIdx.y;
    int x = bx * 32 + tx;
    #pragma unroll
    for (int i = 0; i < 32; i += 8)
        t[ty + i][tx] = src[(size_t)(by * 32 + ty + i) * C + x];
    __syncthreads();
    int x2 = by * 32 + tx;
    #pragma unroll
    for (int i = 0; i < 32; i += 8)
        dst[(size_t)(bx * 32 + ty + i) * R + x2] = __float2half(t[tx][ty + i]);
}

// ---------------- per-window V transpose (fp16) -----------------------------
__global__ __launch_bounds__(256) void vtrans_kernel()
{
    __shared__ __half t[32][34];
    int wb = blockIdx.z;
    int d0 = blockIdx.x * 32, k0 = blockIdx.y * 32;
    int tx = threadIdx.x, ty = threadIdx.y;
    const __half* src = g_VW + (size_t)wb * 32768;
    #pragma unroll
    for (int i = 0; i < 32; i += 8)
        t[ty + i][tx] = src[(size_t)(k0 + ty + i) * 128 + d0 + tx];
    __syncthreads();
    __half* dst = g_VWt + (size_t)wb * 32768;
    #pragma unroll
    for (int i = 0; i < 32; i += 8)
        dst[(size_t)(d0 + ty + i) * 256 + k0 + tx] = t[tx][ty + i];
}

// ---------------- fp16 mma.sync GEMM: C[M,N] = A[M,K] @ Bt[N,K]^T -----------
// 128x128x32 CTA tile, 8 warps (4m x 2n), m16n8k16. PADH=40 halves: the 8
// ldmatrix rows start at banks {20r mod 32} and tile all 32 banks exactly.
#define PADH 40
#define HT_ELEMS (128*PADH)       // 5120 halves per buffer

__device__ __forceinline__ void load_tile_h(__half* dst, const __half* __restrict__ G,
                                            int ld, size_t row0, int col0, int tid)
{
    #pragma unroll
    for (int i = 0; i < 2; i++) {
        int idx = tid + i * 256;
        int row = idx >> 2, c8 = (idx & 3) * 8;
        cpasync16(smem_u32(dst + row * PADH + c8),
                  G + (row0 + row) * (size_t)ld + col0 + c8);
    }
}

template<int OUTH, int ACT>
__global__ __launch_bounds__(256, 2) void gemm_h(const __half* __restrict__ A,
                                                 const __half* __restrict__ Bt,
                                                 void* __restrict__ Cv,
                                                 int M, int N, int K)
{
    __shared__ __half smem[4 * HT_ELEMS];   // A0 A1 B0 B1 = 40960 bytes
    __half* sA[2] = { smem,                smem + HT_ELEMS };
    __half* sBb[2] = { smem + 2 * HT_ELEMS, smem + 3 * HT_ELEMS };

    int tid = threadIdx.x, wid = tid >> 5, lane = tid & 31;
    int wm = wid & 3, wn = wid >> 2;
    size_t m0 = (size_t)blockIdx.y * 128;
    int n0 = blockIdx.x * 128;
    const int nk = K >> 5;

    float acc[2][8][4];
    #pragma unroll
    for (int mt = 0; mt < 2; mt++)
        #pragma unroll
        for (int nt = 0; nt < 8; nt++)
            #pragma unroll
            for (int i = 0; i < 4; i++) acc[mt][nt][i] = 0.f;

    int mat = lane >> 3, mr = lane & 7;
    int a_row = wm * 32 + (mat & 1) * 8 + mr;     // + mt*16
    int a_k8  = (mat >> 1) * 8;
    int b_n   = wn * 64 + (mat >> 1) * 8 + mr;    // + h*16
    int b_k8  = (mat & 1) * 8;

    load_tile_h(sA[0], A, K, m0, 0, tid);
    load_tile_h(sBb[0], Bt, K, (size_t)n0, 0, tid);
    asm volatile("cp.async.commit_group;");

    for (int kt = 0; kt < nk; kt++) {
        int b = kt & 1;
        if (kt + 1 < nk) {
            load_tile_h(sA[b ^ 1], A, K, m0, (kt + 1) * 32, tid);
            load_tile_h(sBb[b ^ 1], Bt, K, (size_t)n0, (kt + 1) * 32, tid);
            asm volatile("cp.async.commit_group;");
            asm volatile("cp.async.wait_group 1;");
        } else {
            asm volatile("cp.async.wait_group 0;");
        }
        __syncthreads();

        uint32_t uA = smem_u32(sA[b]);
        uint32_t uB = smem_u32(sBb[b]);
        #pragma unroll
        for (int ks = 0; ks < 2; ks++) {
            uint32_t a[2][4], bb[4][4];
            #pragma unroll
            for (int mt = 0; mt < 2; mt++)
                ldmx4(uA + (uint32_t)(((a_row + mt * 16) * PADH + ks * 16 + a_k8) * 2),
                      a[mt][0], a[mt][1], a[mt][2], a[mt][3]);
            #pragma unroll
            for (int h = 0; h < 4; h++)
                ldmx4(uB + (uint32_t)(((b_n + h * 16) * PADH + ks * 16 + b_k8) * 2),
                      bb[h][0], bb[h][1], bb[h][2], bb[h][3]);
            #pragma unroll
            for (int mt = 0; mt < 2; mt++)
                #pragma unroll
                for (int nt = 0; nt < 8; nt++)
                    mma_h(acc[mt][nt], a[mt],
                          bb[nt >> 1][(nt & 1) * 2], bb[nt >> 1][(nt & 1) * 2 + 1]);
        }
        __syncthreads();
    }

    int er = lane >> 2, ec = (lane & 3) * 2;
    #pragma unroll
    for (int mt = 0; mt < 2; mt++) {
        size_t r0 = m0 + wm * 32 + mt * 16 + er;
        #pragma unroll
        for (int nt = 0; nt < 8; nt++) {
            int c0 = n0 + wn * 64 + nt * 8 + ec;
            float v0 = acc[mt][nt][0], v1 = acc[mt][nt][1];
            float v2 = acc[mt][nt][2], v3 = acc[mt][nt][3];
            if (ACT) {
                v0 = gelu_exact(v0); v1 = gelu_exact(v1);
                v2 = gelu_exact(v2); v3 = gelu_exact(v3);
            }
            if (OUTH) {
                __half* C = (__half*)Cv;
                *(__half2*)(C + r0 * N + c0)       = __floats2half2_rn(v0, v1);
                *(__half2*)(C + (r0 + 8) * N + c0) = __floats2half2_rn(v2, v3);
            } else {
                float* C = (float*)Cv;
                *(float2*)(C + r0 * N + c0)       = make_float2(v0, v1);
                *(float2*)(C + (r0 + 8) * N + c0) = make_float2(v2, v3);
            }
        }
    }
}

// ---------------- permutation: token -> shifted-window layout (fp16 out) ----
__global__ __launch_bounds__(256) void perm_kernel(const float* __restrict__ src,
                                                   const float* __restrict__ tgt)
{
    int warp = (blockIdx.x * 256 + threadIdx.x) >> 5;
    int lane = threadIdx.x & 31;
    if (warp >= ROWS) return;
    int b   = warp >> 14;
    int wr  = warp & 16383;
    int win = wr >> 8;
    int pos = wr & 255;
    int ip = ((win >> 3) << 4) + (pos >> 4);
    int jp = ((win & 7) << 4) + (pos & 15);
    int i = (ip + 8) & 127;
    int j = (jp + 8) & 127;
    size_t srow = ((size_t)b * LTOK + (size_t)i * WWID + j) * CC;
    size_t drow = (size_t)warp * CC;
    float4 s4 = ((const float4*)(src + srow))[lane];
    float4 t4 = ((const float4*)(tgt + srow))[lane];
    ((__half2*)(g_Sg + drow))[lane * 2]     = __floats2half2_rn(s4.x, s4.y);
    ((__half2*)(g_Sg + drow))[lane * 2 + 1] = __floats2half2_rn(s4.z, s4.w);
    ((__half2*)(g_Tg + drow))[lane * 2]     = __floats2half2_rn(t4.x, t4.y);
    ((__half2*)(g_Tg + drow))[lane * 2 + 1] = __floats2half2_rn(t4.z, t4.w);
}

// ---------------- windowed attention via fp16 mma.sync ----------------------
// CTA = quarter window (64 q rows), 256 threads / 8 warps.
// smem bytes: Q half[64][136] | K/Vt half (<=128*72) | S fp32[64][260] |
//             P half[64][264] | inv fp32[64]
#define AQ 0
#define AK 17408
#define AS 35840
#define AP 102400
#define AI 136192
#define AT_SMEM_BYTES 136448

__device__ __forceinline__ int region3(int x) { return (x < 112) ? 0 : ((x < 120) ? 1 : 2); }
__device__ __forceinline__ int posid(int p, int wr, int wc) {
    return region3(wr * 16 + (p >> 4)) * 3 + region3(wc * 16 + (p & 15));
}

__global__ __launch_bounds__(256) void attn_mma()
{
    extern __shared__ char sm[];
    uint32_t sB = smem_u32(sm);
    __half* Qs = (__half*)(sm + AQ);
    __half* KVs = (__half*)(sm + AK);
    float*  Ss = (float*)(sm + AS);
    __half* Ps = (__half*)(sm + AP);
    float*  Is = (float*)(sm + AI);

    const int tid = threadIdx.x;
    const int lane = tid & 31, w = tid >> 5;
    const int wb = blockIdx.x >> 2, quar = blockIdx.x & 3;
    const int q0 = quar * 64;
    const int win = wb & 63, wr = win >> 3, wc = win & 7;
    const size_t wbase = (size_t)wb * 256 * 128;

    const int wm = w & 3, wn = w >> 2;
    const int mat = lane >> 3, mr = lane & 7;
    const int a_row = wm * 16 + (mat & 1) * 8 + mr;
    const int a_k8  = (mat >> 1) * 8;
    const int bn_off = (mat >> 1) * 8 + mr;
    const int b_k8   = (mat & 1) * 8;
    const int er = lane >> 2, ec = (lane & 3) * 2;

    // ---- load Q (64 rows x 128 halves) into [64][136] ----
    {
        #pragma unroll
        for (int i = 0; i < 4; i++) {
            int idx = tid + i * 256;
            int row = idx >> 4, c8 = (idx & 15) * 8;
            *(uint4*)(Qs + row * 136 + c8) =
                *(const uint4*)(g_QW + wbase + (size_t)(q0 + row) * 128 + c8);
        }
    }

    const int rq = wm * 16 + er;
    const int idq0 = posid(q0 + rq, wr, wc);
    const int idq1 = posid(q0 + rq + 8, wr, wc);
    const float SC = 0.08838834764831845f;

    // ---- phase A: S = Q @ K^T ----
    for (int kb = 0; kb < 4; kb++) {
        __syncthreads();
        #pragma unroll
        for (int i = 0; i < 4; i++) {     // K block: 64 keys x 128 halves -> [64][136]
            int idx = tid + i * 256;
            int row = idx >> 4, c8 = (idx & 15) * 8;
            *(uint4*)(KVs + row * 136 + c8) =
                *(const uint4*)(g_KW + wbase + (size_t)(kb * 64 + row) * 128 + c8);
        }
        __syncthreads();

        float sacc[4][4];
        #pragma unroll
        for (int nt = 0; nt < 4; nt++)
            #pragma unroll
            for (int i = 0; i < 4; i++) sacc[nt][i] = 0.f;

        #pragma unroll
        for (int ks = 0; ks < 8; ks++) {
            uint32_t a[4], bbf[2][4];
            ldmx4(sB + (uint32_t)(AQ + (a_row * 136 + ks * 16 + a_k8) * 2),
                  a[0], a[1], a[2], a[3]);
            #pragma unroll
            for (int h = 0; h < 2; h++)
                ldmx4(sB + (uint32_t)(AK + ((wn * 32 + h * 16 + bn_off) * 136 + ks * 16 + b_k8) * 2),
                      bbf[h][0], bbf[h][1], bbf[h][2], bbf[h][3]);
            #pragma unroll
            for (int nt = 0; nt < 4; nt++)
                mma_h(sacc[nt], a, bbf[nt >> 1][(nt & 1) * 2], bbf[nt >> 1][(nt & 1) * 2 + 1]);
        }

        #pragma unroll
        for (int nt = 0; nt < 4; nt++) {
            int key = kb * 64 + wn * 32 + nt * 8 + ec;
            int idk0 = posid(key, wr, wc), idk1 = posid(key + 1, wr, wc);
            float2 v0, v1;
            v0.x = sacc[nt][0] * SC + ((idq0 == idk0) ? 0.f : -100.f);
            v0.y = sacc[nt][1] * SC + ((idq0 == idk1) ? 0.f : -100.f);
            v1.x = sacc[nt][2] * SC + ((idq1 == idk0) ? 0.f : -100.f);
            v1.y = sacc[nt][3] * SC + ((idq1 == idk1) ? 0.f : -100.f);
            *(float2*)(Ss + rq * 260 + key)       = v0;
            *(float2*)(Ss + (rq + 8) * 260 + key) = v1;
        }
    }
    __syncthreads();

    // ---- softmax: 4 threads/row, stride-4; write P as fp16 ----
    {
        int row = tid >> 2, sub = tid & 3;
        float* sr = Ss + row * 260 + sub;
        __half* pr = Ps + row * 264 + sub;
        float mx = -1e30f;
        #pragma unroll 8
        for (int i = 0; i < 64; i++) mx = fmaxf(mx, sr[i * 4]);
        mx = fmaxf(mx, __shfl_xor_sync(0xffffffffu, mx, 1));
        mx = fmaxf(mx, __shfl_xor_sync(0xffffffffu, mx, 2));
        float s = 0.f;
        #pragma unroll 8
        for (int i = 0; i < 64; i++) {
            float p = __expf(sr[i * 4] - mx);
            pr[i * 4] = __float2half(p);
            s += p;
        }
        s += __shfl_xor_sync(0xffffffffu, s, 1);
        s += __shfl_xor_sync(0xffffffffu, s, 2);
        if (sub == 0) Is[row] = 1.0f / s;
    }

    // ---- phase B: O = P @ V (B from pre-transposed g_VWt) ----
    float oacc[8][4];
    #pragma unroll
    for (int nt = 0; nt < 8; nt++)
        #pragma unroll
        for (int i = 0; i < 4; i++) oacc[nt][i] = 0.f;

    for (int kb = 0; kb < 4; kb++) {
        __syncthreads();
        #pragma unroll
        for (int i = 0; i < 4; i++) {     // Vt block: 128 dims x 64 keys -> [128][72]
            int idx = tid + i * 256;
            int row = idx >> 3, c8 = (idx & 7) * 8;
            *(uint4*)(KVs + row * 72 + c8) =
                *(const uint4*)(g_VWt + (size_t)wb * 32768 + (size_t)row * 256 + kb * 64 + c8);
        }
        __syncthreads();

        #pragma unroll
        for (int ks = 0; ks < 4; ks++) {
            uint32_t a[4], bv[4][4];
            ldmx4(sB + (uint32_t)(AP + (a_row * 264 + kb * 64 + ks * 16 + a_k8) * 2),
                  a[0], a[1], a[2], a[3]);
            #pragma unroll
            for (int h = 0; h < 4; h++)
                ldmx4(sB + (uint32_t)(AK + ((wn * 64 + h * 16 + bn_off) * 72 + ks * 16 + b_k8) * 2),
                      bv[h][0], bv[h][1], bv[h][2], bv[h][3]);
            #pragma unroll
            for (int nt = 0; nt < 8; nt++)
                mma_h(oacc[nt], a, bv[nt >> 1][(nt & 1) * 2], bv[nt >> 1][(nt & 1) * 2 + 1]);
        }
    }

    // ---- epilogue: scale by 1/sum, store fp16 (feeds Wm gemm) ----
    {
        float i0 = Is[rq], i1 = Is[rq + 8];
        __half* op = g_ATT + wbase + (size_t)(q0 + rq) * 128;
        #pragma unroll
        for (int nt = 0; nt < 8; nt++) {
            int dim = wn * 64 + nt * 8 + ec;
            *(__half2*)(op + dim) =
                __floats2half2_rn(oacc[nt][0] * i0, oacc[nt][1] * i0);
            *(__half2*)(op + 8 * 128 + dim) =
                __floats2half2_rn(oacc[nt][2] * i1, oacc[nt][3] * i1);
        }
    }
}

// ---------------- LN(msg) + un-shift gather + concat (fp16 out) -------------
__global__ __launch_bounds__(256) void ln_concat_kernel(const float* __restrict__ src,
                                                        const float* __restrict__ g1,
                                                        const float* __restrict__ b1)
{
    int warp = (blockIdx.x * 256 + threadIdx.x) >> 5;
    int lane = threadIdx.x & 31;
    if (warp >= ROWS) return;
    int b   = warp >> 14;
    int tok = warp & 16383;
    int i = tok >> 7, j = tok & 127;
    int ip = (i + 120) & 127;
    int jp = (j + 120) & 127;
    int win = ((ip >> 4) << 3) + (jp >> 4);
    int pos = ((ip & 15) << 4) + (jp & 15);
    size_t mrow = ((size_t)b * NWIN + win) * WSZ + pos;

    float4 mv = ((const float4*)(g_MSG + mrow * CC))[lane];
    float s  = mv.x + mv.y + mv.z + mv.w;
    float ss = mv.x * mv.x + mv.y * mv.y + mv.z * mv.z + mv.w * mv.w;
    #pragma unroll
    for (int o = 16; o > 0; o >>= 1) {
        s  += __shfl_xor_sync(0xffffffffu, s,  o);
        ss += __shfl_xor_sync(0xffffffffu, ss, o);
    }
    float mean = s * (1.0f / 128.0f);
    float var  = ss * (1.0f / 128.0f) - mean * mean;
    float r = rsqrtf(var + 1e-5f);
    float4 gv = ((const float4*)g1)[lane];
    float4 bv = ((const float4*)b1)[lane];
    float o0 = (mv.x - mean) * r * gv.x + bv.x;
    float o1 = (mv.y - mean) * r * gv.y + bv.y;
    float o2 = (mv.z - mean) * r * gv.z + bv.z;
    float o3 = (mv.w - mean) * r * gv.w + bv.w;

    float4 sv = ((const float4*)(src + (size_t)warp * CC))[lane];

    __half* frow = g_FIN + (size_t)warp * (2 * CC);
    ((__half2*)(frow))[lane * 2]           = __floats2half2_rn(sv.x, sv.y);
    ((__half2*)(frow))[lane * 2 + 1]       = __floats2half2_rn(sv.z, sv.w);
    ((__half2*)(frow + CC))[lane * 2]      = __floats2half2_rn(o0, o1);
    ((__half2*)(frow + CC))[lane * 2 + 1]  = __floats2half2_rn(o2, o3);
}

// ---------------- final LN + residual ---------------------------------------
__global__ __launch_bounds__(256) void ln_res_kernel(const float* __restrict__ src,
                                                     const float* __restrict__ g2,
                                                     const float* __restrict__ b2,
                                                     float* __restrict__ out)
{
    int warp = (blockIdx.x * 256 + threadIdx.x) >> 5;
    int lane = threadIdx.x & 31;
    if (warp >= ROWS) return;

    float4 mv = ((const float4*)(g_MSG2 + (size_t)warp * CC))[lane];
    float s  = mv.x + mv.y + mv.z + mv.w;
    float ss = mv.x * mv.x + mv.y * mv.y + mv.z * mv.z + mv.w * mv.w;
    #pragma unroll
    for (int o = 16; o > 0; o >>= 1) {
        s  += __shfl_xor_sync(0xffffffffu, s,  o);
        ss += __shfl_xor_sync(0xffffffffu, ss, o);
    }
    float mean = s * (1.0f / 128.0f);
    float var  = ss * (1.0f / 128.0f) - mean * mean;
    float r = rsqrtf(var + 1e-5f);
    float4 gv = ((const float4*)g2)[lane];
    float4 bv = ((const float4*)b2)[lane];
    float4 sv = ((const float4*)(src + (size_t)warp * CC))[lane];
    float4 o4;
    o4.x = sv.x + (mv.x - mean) * r * gv.x + bv.x;
    o4.y = sv.y + (mv.y - mean) * r * gv.y + bv.y;
    o4.z = sv.z + (mv.z - mean) * r * gv.z + bv.z;
    o4.w = sv.w + (mv.w - mean) * r * gv.w + bv.w;
    ((float4*)(out + (size_t)warp * CC))[lane] = o4;
}

// ---------------- host launcher ---------------------------------------------
extern "C" void kernel_launch(void* const* d_in, const int* in_sizes, int n_in,
                              void* d_out, int out_size)
{
    const float* src = (const float*)d_in[0];
    const float* tgt = (const float*)d_in[1];
    const float* Wq  = (const float*)d_in[2];
    const float* Wk  = (const float*)d_in[3];
    const float* Wv  = (const float*)d_in[4];
    const float* Wm  = (const float*)d_in[5];
    const float* g1  = (const float*)d_in[6];
    const float* b1  = (const float*)d_in[7];
    const float* W1  = (const float*)d_in[8];
    const float* W2  = (const float*)d_in[9];
    const float* g2  = (const float*)d_in[10];
    const float* b2  = (const float*)d_in[11];

    __half *Sg, *Tg, *QW, *KW, *VW, *ATT, *FIN, *HIDp;
    __half *WqT, *WkT, *WvT, *WmT, *W1T, *W2T;
    float *MSG, *MSG2;
    cudaGetSymbolAddress((void**)&Sg,   g_Sg);
    cudaGetSymbolAddress((void**)&Tg,   g_Tg);
    cudaGetSymbolAddress((void**)&QW,   g_QW);
    cudaGetSymbolAddress((void**)&KW,   g_KW);
    cudaGetSymbolAddress((void**)&VW,   g_VW);
    cudaGetSymbolAddress((void**)&ATT,  g_ATT);
    cudaGetSymbolAddress((void**)&MSG,  g_MSG);
    cudaGetSymbolAddress((void**)&FIN,  g_FIN);
    cudaGetSymbolAddress((void**)&HIDp, g_HID);
    cudaGetSymbolAddress((void**)&MSG2, g_MSG2);
    cudaGetSymbolAddress((void**)&WqT,  g_WqT);
    cudaGetSymbolAddress((void**)&WkT,  g_WkT);
    cudaGetSymbolAddress((void**)&WvT,  g_WvT);
    cudaGetSymbolAddress((void**)&WmT,  g_WmT);
    cudaGetSymbolAddress((void**)&W1T,  g_W1T);
    cudaGetSymbolAddress((void**)&W2T,  g_W2T);

    cudaFuncSetAttribute(attn_mma, cudaFuncAttributeMaxDynamicSharedMemorySize,
                         AT_SMEM_BYTES);

    // 1) all weight transposes in one launch (fp32 -> fp16 [N,K])
    transpose_all<<<448, dim3(32, 8)>>>(Wq, Wk, Wv, Wm, W1, W2);

    // 2) shift + window partition (fp16 out)
    perm_kernel<<<4096, 256>>>(src, tgt);

    // 3) Q and V projections, then per-window V transpose, then K projection
    gemm_h<1, 0><<<dim3(1, 256), 256>>>(Sg, WqT, QW, ROWS, 128, 128);
    gemm_h<1, 0><<<dim3(1, 256), 256>>>(Tg, WvT, VW, ROWS, 128, 128);
    vtrans_kernel<<<dim3(4, 8, 128), dim3(32, 8)>>>();
    gemm_h<1, 0><<<dim3(1, 256), 256>>>(Tg, WkT, KW, ROWS, 128, 128);

    // 4) shifted-window attention (fp16 mma.sync)
    attn_mma<<<4 * BB * NWIN, 256, AT_SMEM_BYTES>>>();

    // 5) message projection (fp32 out -> LayerNorm)
    gemm_h<0, 0><<<dim3(1, 256), 256>>>(ATT, WmT, MSG, ROWS, 128, 128);

    // 6) LN(msg) + un-shift + concat (fp16 out)
    ln_concat_kernel<<<4096, 256>>>(src, g1, b1);

    // 7) FFN
    gemm_h<1, 1><<<dim3(8, 256), 256>>>(FIN, W1T, HIDp, ROWS, HIDN, 2 * CC);
    gemm_h<0, 0><<<dim3(1, 256), 256>>>(HIDp, W2T, MSG2, ROWS, 128, HIDN);

    // 8) final LN + residual
    ln_res_kernel<<<4096, 256>>>(src, g2, b2, (float*)d_out);
}

// round 6
// speedup vs baseline: 4.2249x; 1.0659x over previous
#include <cuda_runtime.h>
#include <cuda_fp16.h>
#include <math.h>
#include <stdint.h>

// Problem constants
#define BB   2
#define HH   128
#define WWID 128
#define CC   128
#define NWIN 64
#define WSZ  256
#define LTOK (HH*WWID)     // 16384
#define ROWS (BB*LTOK)     // 32768
#define HIDN 1024

// ---------------- scratch ---------------------------------------------------
__device__ __half g_QW[ROWS*CC];
__device__ __half g_KW[ROWS*CC];
__device__ __half g_VW[ROWS*CC];
__device__ __half g_VWt[ROWS*CC];          // per-window transposed V: [wb][dim][key]
__device__ __half g_ATT[ROWS*CC];
__device__ float  g_MSG[ROWS*CC];          // fp32 (feeds LayerNorm)
__device__ __half g_FIN[(size_t)ROWS*2*CC];
__device__ __half g_HID[(size_t)ROWS*HIDN];
__device__ float  g_MSG2[ROWS*CC];         // fp32 (feeds LayerNorm)
// transposed weights [N, K] in fp16
__device__ __half g_WqT[CC*CC];
__device__ __half g_WkvT[2*CC*CC];         // [WkT ; WvT]
__device__ __half g_WmT[CC*CC];
__device__ __half g_W1T[HIDN*2*CC];
__device__ __half g_W2T[CC*HIDN];

// ---------------- helpers ---------------------------------------------------
__device__ __forceinline__ float gelu_exact(float x) {
    return 0.5f * x * (1.0f + erff(x * 0.70710678118654752f));
}
__device__ __forceinline__ uint32_t smem_u32(const void* p) {
    uint32_t a;
    asm("{ .reg .u64 t; cvta.to.shared.u64 t, %1; cvt.u32.u64 %0, t; }" : "=r"(a) : "l"(p));
    return a;
}
__device__ __forceinline__ void cpasync16(uint32_t dst, const __half* src) {
    asm volatile("cp.async.cg.shared.global [%0], [%1], 16;" :: "r"(dst), "l"(src));
}
__device__ __forceinline__ void ldmx4(uint32_t addr, uint32_t& d0, uint32_t& d1,
                                      uint32_t& d2, uint32_t& d3) {
    asm volatile("ldmatrix.sync.aligned.m8n8.x4.shared.b16 {%0,%1,%2,%3}, [%4];"
                 : "=r"(d0), "=r"(d1), "=r"(d2), "=r"(d3) : "r"(addr));
}
__device__ __forceinline__ void mma_h(float* c, const uint32_t* a, uint32_t b0, uint32_t b1) {
    asm volatile("mma.sync.aligned.m16n8k16.row.col.f32.f16.f16.f32 "
                 "{%0,%1,%2,%3}, {%4,%5,%6,%7}, {%8,%9}, {%0,%1,%2,%3};"
                 : "+f"(c[0]), "+f"(c[1]), "+f"(c[2]), "+f"(c[3])
                 : "r"(a[0]), "r"(a[1]), "r"(a[2]), "r"(a[3]), "r"(b0), "r"(b1));
}

// ---------------- batched weight transpose: fp32 [R,C] -> fp16 [C,R] --------
__global__ __launch_bounds__(256) void transpose_all(const float* __restrict__ Wq,
                                                     const float* __restrict__ Wk,
                                                     const float* __restrict__ Wv,
                                                     const float* __restrict__ Wm,
                                                     const float* __restrict__ W1,
                                                     const float* __restrict__ W2)
{
    __shared__ float t[32][33];
    int id = blockIdx.x;
    const float* src; __half* dst; int R, C, bx, by;
    if (id < 64) {
        int wsel = id >> 4, tt = id & 15;
        bx = tt & 3; by = tt >> 2; R = 128; C = 128;
        src = (wsel == 0) ? Wq : (wsel == 1) ? Wk : (wsel == 2) ? Wv : Wm;
        dst = (wsel == 0) ? g_WqT : (wsel == 1) ? g_WkvT
            : (wsel == 2) ? (g_WkvT + 128 * 128) : g_WmT;
    } else if (id < 320) {
        int tt = id - 64; bx = tt & 31; by = tt >> 5; R = 256; C = 1024;
        src = W1; dst = g_W1T;
    } else {
        int tt = id - 320; bx = tt & 3; by = tt >> 2; R = 1024; C = 128;
        src = W2; dst = g_W2T;
    }
    int tx = threadIdx.x, ty = threadIdx.y;
    int x = bx * 32 + tx;
    #pragma unroll
    for (int i = 0; i < 32; i += 8)
        t[ty + i][tx] = src[(size_t)(by * 32 + ty + i) * C + x];
    __syncthreads();
    int x2 = by * 32 + tx;
    #pragma unroll
    for (int i = 0; i < 32; i += 8)
        dst[(size_t)(bx * 32 + ty + i) * R + x2] = __float2half(t[tx][ty + i]);
}

// ---------------- per-window V transpose (fp16) -----------------------------
__global__ __launch_bounds__(256) void vtrans_kernel()
{
    __shared__ __half t[32][34];
    int wb = blockIdx.z;
    int d0 = blockIdx.x * 32, k0 = blockIdx.y * 32;
    int tx = threadIdx.x, ty = threadIdx.y;
    const __half* src = g_VW + (size_t)wb * 32768;
    #pragma unroll
    for (int i = 0; i < 32; i += 8)
        t[ty + i][tx] = src[(size_t)(k0 + ty + i) * 128 + d0 + tx];
    __syncthreads();
    __half* dst = g_VWt + (size_t)wb * 32768;
    #pragma unroll
    for (int i = 0; i < 32; i += 8)
        dst[(size_t)(d0 + ty + i) * 256 + k0 + tx] = t[tx][ty + i];
}

// ---------------- one-shot K=128 GEMM ---------------------------------------
// C[m, 0:128] = A[m, 0:128] @ Bt[nb*128 + (0:128), 0:128]^T
// A is either fp32 token-layout source with window-permuted rows (PERM=1),
// or fp16 windowed-layout (PERM=0). Whole K resident: one sync, no mainloop
// stalls. smem = 2 * 128 * 136 halves = 69632 B -> 2 CTAs/SM.
#define P1 136

template<int PERM, int OUTH>
__global__ __launch_bounds__(256, 2) void gemm128(const void* __restrict__ Av,
                                                  const __half* __restrict__ Bt,
                                                  void* __restrict__ C0v,
                                                  void* __restrict__ C1v)
{
    extern __shared__ __half smh[];
    __half* sA  = smh;             // [128][136]
    __half* sBt = smh + 128 * P1;  // [128][136]
    int tid = threadIdx.x, wid = tid >> 5, lane = tid & 31;
    int wm = wid & 3, wn = wid >> 2;
    size_t m0 = (size_t)blockIdx.y * 128;
    int nb = blockIdx.x;

    // B tile (always fp16 [N,K]) via cp.async
    #pragma unroll
    for (int i = 0; i < 8; i++) {
        int idx = tid + i * 256;
        int row = idx >> 4, c8 = (idx & 15) * 8;
        cpasync16(smem_u32(sBt + row * P1 + c8),
                  Bt + (size_t)(nb * 128 + row) * 128 + c8);
    }
    asm volatile("cp.async.commit_group;");

    if (PERM) {
        // A: fp32 token layout, window-permuted rows, cvt to fp16
        const float* Af = (const float*)Av;
        int r2 = tid >> 1, hh = tid & 1;
        size_t m = m0 + r2;
        int b = (int)(m >> 14), win = (int)((m >> 8) & 63), pos = (int)(m & 255);
        int ip = ((win >> 3) << 4) + (pos >> 4);
        int jp = ((win & 7) << 4) + (pos & 15);
        int ii = (ip + 8) & 127, jj = (jp + 8) & 127;
        const float* srow = Af + ((size_t)b * LTOK + (size_t)ii * 128 + jj) * 128 + hh * 64;
        __half* drow = sA + r2 * P1 + hh * 64;
        #pragma unroll
        for (int q = 0; q < 16; q++) {
            float4 v = *(const float4*)(srow + q * 4);
            *(__half2*)(drow + q * 4)     = __floats2half2_rn(v.x, v.y);
            *(__half2*)(drow + q * 4 + 2) = __floats2half2_rn(v.z, v.w);
        }
    } else {
        const __half* Ah = (const __half*)Av;
        #pragma unroll
        for (int i = 0; i < 8; i++) {
            int idx = tid + i * 256;
            int row = idx >> 4, c8 = (idx & 15) * 8;
            cpasync16(smem_u32(sA + row * P1 + c8), Ah + (m0 + row) * 128 + c8);
        }
        asm volatile("cp.async.commit_group;");
    }
    asm volatile("cp.async.wait_group 0;");
    __syncthreads();

    float acc[2][8][4] = {};
    int mat = lane >> 3, mr = lane & 7;
    int a_row = wm * 32 + (mat & 1) * 8 + mr;
    int a_k8  = (mat >> 1) * 8;
    int b_n   = wn * 64 + (mat >> 1) * 8 + mr;
    int b_k8  = (mat & 1) * 8;
    uint32_t uA = smem_u32(sA), uB = smem_u32(sBt);

    #pragma unroll
    for (int ks = 0; ks < 8; ks++) {
        uint32_t a[2][4], bb[4][4];
        #pragma unroll
        for (int mt = 0; mt < 2; mt++)
            ldmx4(uA + (uint32_t)(((a_row + mt * 16) * P1 + ks * 16 + a_k8) * 2),
                  a[mt][0], a[mt][1], a[mt][2], a[mt][3]);
        #pragma unroll
        for (int h = 0; h < 4; h++)
            ldmx4(uB + (uint32_t)(((b_n + h * 16) * P1 + ks * 16 + b_k8) * 2),
                  bb[h][0], bb[h][1], bb[h][2], bb[h][3]);
        #pragma unroll
        for (int mt = 0; mt < 2; mt++)
            #pragma unroll
            for (int nt = 0; nt < 8; nt++)
                mma_h(acc[mt][nt], a[mt],
                      bb[nt >> 1][(nt & 1) * 2], bb[nt >> 1][(nt & 1) * 2 + 1]);
    }

    void* Cv = (nb == 0) ? C0v : C1v;
    int er = lane >> 2, ec = (lane & 3) * 2;
    #pragma unroll
    for (int mt = 0; mt < 2; mt++) {
        size_t r0 = m0 + wm * 32 + mt * 16 + er;
        #pragma unroll
        for (int nt = 0; nt < 8; nt++) {
            int c0 = wn * 64 + nt * 8 + ec;
            if (OUTH) {
                __half* C = (__half*)Cv;
                *(__half2*)(C + r0 * 128 + c0) =
                    __floats2half2_rn(acc[mt][nt][0], acc[mt][nt][1]);
                *(__half2*)(C + (r0 + 8) * 128 + c0) =
                    __floats2half2_rn(acc[mt][nt][2], acc[mt][nt][3]);
            } else {
                float* C = (float*)Cv;
                *(float2*)(C + r0 * 128 + c0) =
                    make_float2(acc[mt][nt][0], acc[mt][nt][1]);
                *(float2*)(C + (r0 + 8) * 128 + c0) =
                    make_float2(acc[mt][nt][2], acc[mt][nt][3]);
            }
        }
    }
}

// ---------------- big-K GEMM: 3-stage cp.async pipeline, K-chunk 64 ---------
// C[M,N] = A[M,K] @ Bt[N,K]^T.  smem = 3 stages * (A+B) * 128*72 halves = 108 KB.
#define P2 72
#define ST_ELEMS (128*P2)           // 9216 halves / 18432 bytes per matrix
#define BIG_SMEM (3*2*ST_ELEMS*2)   // 110592 bytes

__device__ __forceinline__ void big_load_stage(__half* smh, int s,
                                               const __half* __restrict__ A,
                                               const __half* __restrict__ Bt,
                                               size_t m0, int n0, int K, int kc, int tid)
{
    __half* dA = smh + s * 2 * ST_ELEMS;
    __half* dB = dA + ST_ELEMS;
    #pragma unroll
    for (int i = 0; i < 4; i++) {
        int idx = tid + i * 256;
        int row = idx >> 3, c8 = (idx & 7) * 8;
        cpasync16(smem_u32(dA + row * P2 + c8), A  + (m0 + row) * (size_t)K + kc * 64 + c8);
        cpasync16(smem_u32(dB + row * P2 + c8), Bt + (size_t)(n0 + row) * K + kc * 64 + c8);
    }
    asm volatile("cp.async.commit_group;");
}

template<int OUTH, int ACT>
__global__ __launch_bounds__(256, 2) void gemm_big(const __half* __restrict__ A,
                                                   const __half* __restrict__ Bt,
                                                   void* __restrict__ Cv,
                                                   int N, int K)
{
    extern __shared__ __half smh[];
    int tid = threadIdx.x, wid = tid >> 5, lane = tid & 31;
    int wm = wid & 3, wn = wid >> 2;
    size_t m0 = (size_t)blockIdx.y * 128;
    int n0 = blockIdx.x * 128;
    const int nk = K >> 6;

    big_load_stage(smh, 0, A, Bt, m0, n0, K, 0, tid);
    big_load_stage(smh, 1, A, Bt, m0, n0, K, 1, tid);

    float acc[2][8][4] = {};
    int mat = lane >> 3, mr = lane & 7;
    int a_row = wm * 32 + (mat & 1) * 8 + mr;
    int a_k8  = (mat >> 1) * 8;
    int b_n   = wn * 64 + (mat >> 1) * 8 + mr;
    int b_k8  = (mat & 1) * 8;

    for (int kt = 0; kt < nk; kt++) {
        if (kt + 2 < nk) {
            big_load_stage(smh, (kt + 2) % 3, A, Bt, m0, n0, K, kt + 2, tid);
            asm volatile("cp.async.wait_group 2;");
        } else if (kt + 1 < nk) {
            asm volatile("cp.async.wait_group 1;");
        } else {
            asm volatile("cp.async.wait_group 0;");
        }
        __syncthreads();

        int s = kt % 3;
        uint32_t uA = smem_u32(smh + s * 2 * ST_ELEMS);
        uint32_t uB = smem_u32(smh + s * 2 * ST_ELEMS + ST_ELEMS);
        #pragma unroll
        for (int ks = 0; ks < 4; ks++) {
            uint32_t a[2][4], bb[4][4];
            #pragma unroll
            for (int mt = 0; mt < 2; mt++)
                ldmx4(uA + (uint32_t)(((a_row + mt * 16) * P2 + ks * 16 + a_k8) * 2),
                      a[mt][0], a[mt][1], a[mt][2], a[mt][3]);
            #pragma unroll
            for (int h = 0; h < 4; h++)
                ldmx4(uB + (uint32_t)(((b_n + h * 16) * P2 + ks * 16 + b_k8) * 2),
                      bb[h][0], bb[h][1], bb[h][2], bb[h][3]);
            #pragma unroll
            for (int mt = 0; mt < 2; mt++)
                #pragma unroll
                for (int nt = 0; nt < 8; nt++)
                    mma_h(acc[mt][nt], a[mt],
                          bb[nt >> 1][(nt & 1) * 2], bb[nt >> 1][(nt & 1) * 2 + 1]);
        }
        __syncthreads();
    }

    int er = lane >> 2, ec = (lane & 3) * 2;
    #pragma unroll
    for (int mt = 0; mt < 2; mt++) {
        size_t r0 = m0 + wm * 32 + mt * 16 + er;
        #pragma unroll
        for (int nt = 0; nt < 8; nt++) {
            int c0 = n0 + wn * 64 + nt * 8 + ec;
            float v0 = acc[mt][nt][0], v1 = acc[mt][nt][1];
            float v2 = acc[mt][nt][2], v3 = acc[mt][nt][3];
            if (ACT) {
                v0 = gelu_exact(v0); v1 = gelu_exact(v1);
                v2 = gelu_exact(v2); v3 = gelu_exact(v3);
            }
            if (OUTH) {
                __half* C = (__half*)Cv;
                *(__half2*)(C + r0 * N + c0)       = __floats2half2_rn(v0, v1);
                *(__half2*)(C + (r0 + 8) * N + c0) = __floats2half2_rn(v2, v3);
            } else {
                float* C = (float*)Cv;
                *(float2*)(C + r0 * N + c0)       = make_float2(v0, v1);
                *(float2*)(C + (r0 + 8) * N + c0) = make_float2(v2, v3);
            }
        }
    }
}

// ---------------- windowed attention via fp16 mma.sync ----------------------
#define AQ 0
#define AK 17408
#define AS 35840
#define AP 102400
#define AI 136192
#define AT_SMEM_BYTES 136448

__device__ __forceinline__ int region3(int x) { return (x < 112) ? 0 : ((x < 120) ? 1 : 2); }
__device__ __forceinline__ int posid(int p, int wr, int wc) {
    return region3(wr * 16 + (p >> 4)) * 3 + region3(wc * 16 + (p & 15));
}

__global__ __launch_bounds__(256) void attn_mma()
{
    extern __shared__ char sm[];
    uint32_t sB = smem_u32(sm);
    __half* Qs = (__half*)(sm + AQ);
    __half* KVs = (__half*)(sm + AK);
    float*  Ss = (float*)(sm + AS);
    __half* Ps = (__half*)(sm + AP);
    float*  Is = (float*)(sm + AI);

    const int tid = threadIdx.x;
    const int lane = tid & 31, w = tid >> 5;
    const int wb = blockIdx.x >> 2, quar = blockIdx.x & 3;
    const int q0 = quar * 64;
    const int win = wb & 63, wr = win >> 3, wc = win & 7;
    const size_t wbase = (size_t)wb * 256 * 128;

    const int wm = w & 3, wn = w >> 2;
    const int mat = lane >> 3, mr = lane & 7;
    const int a_row = wm * 16 + (mat & 1) * 8 + mr;
    const int a_k8  = (mat >> 1) * 8;
    const int bn_off = (mat >> 1) * 8 + mr;
    const int b_k8   = (mat & 1) * 8;
    const int er = lane >> 2, ec = (lane & 3) * 2;

    {
        #pragma unroll
        for (int i = 0; i < 4; i++) {
            int idx = tid + i * 256;
            int row = idx >> 4, c8 = (idx & 15) * 8;
            *(uint4*)(Qs + row * 136 + c8) =
                *(const uint4*)(g_QW + wbase + (size_t)(q0 + row) * 128 + c8);
        }
    }

    const int rq = wm * 16 + er;
    const int idq0 = posid(q0 + rq, wr, wc);
    const int idq1 = posid(q0 + rq + 8, wr, wc);
    const float SC = 0.08838834764831845f;

    for (int kb = 0; kb < 4; kb++) {
        __syncthreads();
        #pragma unroll
        for (int i = 0; i < 4; i++) {
            int idx = tid + i * 256;
            int row = idx >> 4, c8 = (idx & 15) * 8;
            *(uint4*)(KVs + row * 136 + c8) =
                *(const uint4*)(g_KW + wbase + (size_t)(kb * 64 + row) * 128 + c8);
        }
        __syncthreads();

        float sacc[4][4];
        #pragma unroll
        for (int nt = 0; nt < 4; nt++)
            #pragma unroll
            for (int i = 0; i < 4; i++) sacc[nt][i] = 0.f;

        #pragma unroll
        for (int ks = 0; ks < 8; ks++) {
            uint32_t a[4], bbf[2][4];
            ldmx4(sB + (uint32_t)(AQ + (a_row * 136 + ks * 16 + a_k8) * 2),
                  a[0], a[1], a[2], a[3]);
            #pragma unroll
            for (int h = 0; h < 2; h++)
                ldmx4(sB + (uint32_t)(AK + ((wn * 32 + h * 16 + bn_off) * 136 + ks * 16 + b_k8) * 2),
                      bbf[h][0], bbf[h][1], bbf[h][2], bbf[h][3]);
            #pragma unroll
            for (int nt = 0; nt < 4; nt++)
                mma_h(sacc[nt], a, bbf[nt >> 1][(nt & 1) * 2], bbf[nt >> 1][(nt & 1) * 2 + 1]);
        }

        #pragma unroll
        for (int nt = 0; nt < 4; nt++) {
            int key = kb * 64 + wn * 32 + nt * 8 + ec;
            int idk0 = posid(key, wr, wc), idk1 = posid(key + 1, wr, wc);
            float2 v0, v1;
            v0.x = sacc[nt][0] * SC + ((idq0 == idk0) ? 0.f : -100.f);
            v0.y = sacc[nt][1] * SC + ((idq0 == idk1) ? 0.f : -100.f);
            v1.x = sacc[nt][2] * SC + ((idq1 == idk0) ? 0.f : -100.f);
            v1.y = sacc[nt][3] * SC + ((idq1 == idk1) ? 0.f : -100.f);
            *(float2*)(Ss + rq * 260 + key)       = v0;
            *(float2*)(Ss + (rq + 8) * 260 + key) = v1;
        }
    }
    __syncthreads();

    {
        int row = tid >> 2, sub = tid & 3;
        float* sr = Ss + row * 260 + sub;
        __half* pr = Ps + row * 264 + sub;
        float mx = -1e30f;
        #pragma unroll 8
        for (int i = 0; i < 64; i++) mx = fmaxf(mx, sr[i * 4]);
        mx = fmaxf(mx, __shfl_xor_sync(0xffffffffu, mx, 1));
        mx = fmaxf(mx, __shfl_xor_sync(0xffffffffu, mx, 2));
        float s = 0.f;
        #pragma unroll 8
        for (int i = 0; i < 64; i++) {
            float p = __expf(sr[i * 4] - mx);
            pr[i * 4] = __float2half(p);
            s += p;
        }
        s += __shfl_xor_sync(0xffffffffu, s, 1);
        s += __shfl_xor_sync(0xffffffffu, s, 2);
        if (sub == 0) Is[row] = 1.0f / s;
    }

    float oacc[8][4];
    #pragma unroll
    for (int nt = 0; nt < 8; nt++)
        #pragma unroll
        for (int i = 0; i < 4; i++) oacc[nt][i] = 0.f;

    for (int kb = 0; kb < 4; kb++) {
        __syncthreads();
        #pragma unroll
        for (int i = 0; i < 4; i++) {
            int idx = tid + i * 256;
            int row = idx >> 3, c8 = (idx & 7) * 8;
            *(uint4*)(KVs + row * 72 + c8) =
                *(const uint4*)(g_VWt + (size_t)wb * 32768 + (size_t)row * 256 + kb * 64 + c8);
        }
        __syncthreads();

        #pragma unroll
        for (int ks = 0; ks < 4; ks++) {
            uint32_t a[4], bv[4][4];
            ldmx4(sB + (uint32_t)(AP + (a_row * 264 + kb * 64 + ks * 16 + a_k8) * 2),
                  a[0], a[1], a[2], a[3]);
            #pragma unroll
            for (int h = 0; h < 4; h++)
                ldmx4(sB + (uint32_t)(AK + ((wn * 64 + h * 16 + bn_off) * 72 + ks * 16 + b_k8) * 2),
                      bv[h][0], bv[h][1], bv[h][2], bv[h][3]);
            #pragma unroll
            for (int nt = 0; nt < 8; nt++)
                mma_h(oacc[nt], a, bv[nt >> 1][(nt & 1) * 2], bv[nt >> 1][(nt & 1) * 2 + 1]);
        }
    }

    {
        float i0 = Is[rq], i1 = Is[rq + 8];
        __half* op = g_ATT + wbase + (size_t)(q0 + rq) * 128;
        #pragma unroll
        for (int nt = 0; nt < 8; nt++) {
            int dim = wn * 64 + nt * 8 + ec;
            *(__half2*)(op + dim) =
                __floats2half2_rn(oacc[nt][0] * i0, oacc[nt][1] * i0);
            *(__half2*)(op + 8 * 128 + dim) =
                __floats2half2_rn(oacc[nt][2] * i1, oacc[nt][3] * i1);
        }
    }
}

// ---------------- LN(msg) + un-shift gather + concat (fp16 out) -------------
__global__ __launch_bounds__(256) void ln_concat_kernel(const float* __restrict__ src,
                                                        const float* __restrict__ g1,
                                                        const float* __restrict__ b1)
{
    int warp = (blockIdx.x * 256 + threadIdx.x) >> 5;
    int lane = threadIdx.x & 31;
    if (warp >= ROWS) return;
    int b   = warp >> 14;
    int tok = warp & 16383;
    int i = tok >> 7, j = tok & 127;
    int ip = (i + 120) & 127;
    int jp = (j + 120) & 127;
    int win = ((ip >> 4) << 3) + (jp >> 4);
    int pos = ((ip & 15) << 4) + (jp & 15);
    size_t mrow = ((size_t)b * NWIN + win) * WSZ + pos;

    float4 mv = ((const float4*)(g_MSG + mrow * CC))[lane];
    float s  = mv.x + mv.y + mv.z + mv.w;
    float ss = mv.x * mv.x + mv.y * mv.y + mv.z * mv.z + mv.w * mv.w;
    #pragma unroll
    for (int o = 16; o > 0; o >>= 1) {
        s  += __shfl_xor_sync(0xffffffffu, s,  o);
        ss += __shfl_xor_sync(0xffffffffu, ss, o);
    }
    float mean = s * (1.0f / 128.0f);
    float var  = ss * (1.0f / 128.0f) - mean * mean;
    float r = rsqrtf(var + 1e-5f);
    float4 gv = ((const float4*)g1)[lane];
    float4 bv = ((const float4*)b1)[lane];
    float o0 = (mv.x - mean) * r * gv.x + bv.x;
    float o1 = (mv.y - mean) * r * gv.y + bv.y;
    float o2 = (mv.z - mean) * r * gv.z + bv.z;
    float o3 = (mv.w - mean) * r * gv.w + bv.w;

    float4 sv = ((const float4*)(src + (size_t)warp * CC))[lane];

    __half* frow = g_FIN + (size_t)warp * (2 * CC);
    ((__half2*)(frow))[lane * 2]           = __floats2half2_rn(sv.x, sv.y);
    ((__half2*)(frow))[lane * 2 + 1]       = __floats2half2_rn(sv.z, sv.w);
    ((__half2*)(frow + CC))[lane * 2]      = __floats2half2_rn(o0, o1);
    ((__half2*)(frow + CC))[lane * 2 + 1]  = __floats2half2_rn(o2, o3);
}

// ---------------- final LN + residual ---------------------------------------
__global__ __launch_bounds__(256) void ln_res_kernel(const float* __restrict__ src,
                                                     const float* __restrict__ g2,
                                                     const float* __restrict__ b2,
                                                     float* __restrict__ out)
{
    int warp = (blockIdx.x * 256 + threadIdx.x) >> 5;
    int lane = threadIdx.x & 31;
    if (warp >= ROWS) return;

    float4 mv = ((const float4*)(g_MSG2 + (size_t)warp * CC))[lane];
    float s  = mv.x + mv.y + mv.z + mv.w;
    float ss = mv.x * mv.x + mv.y * mv.y + mv.z * mv.z + mv.w * mv.w;
    #pragma unroll
    for (int o = 16; o > 0; o >>= 1) {
        s  += __shfl_xor_sync(0xffffffffu, s,  o);
        ss += __shfl_xor_sync(0xffffffffu, ss, o);
    }
    float mean = s * (1.0f / 128.0f);
    float var  = ss * (1.0f / 128.0f) - mean * mean;
    float r = rsqrtf(var + 1e-5f);
    float4 gv = ((const float4*)g2)[lane];
    float4 bv = ((const float4*)b2)[lane];
    float4 sv = ((const float4*)(src + (size_t)warp * CC))[lane];
    float4 o4;
    o4.x = sv.x + (mv.x - mean) * r * gv.x + bv.x;
    o4.y = sv.y + (mv.y - mean) * r * gv.y + bv.y;
    o4.z = sv.z + (mv.z - mean) * r * gv.z + bv.z;
    o4.w = sv.w + (mv.w - mean) * r * gv.w + bv.w;
    ((float4*)(out + (size_t)warp * CC))[lane] = o4;
}

// ---------------- host launcher ---------------------------------------------
extern "C" void kernel_launch(void* const* d_in, const int* in_sizes, int n_in,
                              void* d_out, int out_size)
{
    const float* src = (const float*)d_in[0];
    const float* tgt = (const float*)d_in[1];
    const float* Wq  = (const float*)d_in[2];
    const float* Wk  = (const float*)d_in[3];
    const float* Wv  = (const float*)d_in[4];
    const float* Wm  = (const float*)d_in[5];
    const float* g1  = (const float*)d_in[6];
    const float* b1  = (const float*)d_in[7];
    const float* W1  = (const float*)d_in[8];
    const float* W2  = (const float*)d_in[9];
    const float* g2  = (const float*)d_in[10];
    const float* b2  = (const float*)d_in[11];

    __half *QW, *KW, *VW, *ATT, *FIN, *HIDp;
    __half *WqT, *WkvT, *WmT, *W1T, *W2T;
    float *MSG, *MSG2;
    cudaGetSymbolAddress((void**)&QW,   g_QW);
    cudaGetSymbolAddress((void**)&KW,   g_KW);
    cudaGetSymbolAddress((void**)&VW,   g_VW);
    cudaGetSymbolAddress((void**)&ATT,  g_ATT);
    cudaGetSymbolAddress((void**)&MSG,  g_MSG);
    cudaGetSymbolAddress((void**)&FIN,  g_FIN);
    cudaGetSymbolAddress((void**)&HIDp, g_HID);
    cudaGetSymbolAddress((void**)&MSG2, g_MSG2);
    cudaGetSymbolAddress((void**)&WqT,  g_WqT);
    cudaGetSymbolAddress((void**)&WkvT, g_WkvT);
    cudaGetSymbolAddress((void**)&WmT,  g_WmT);
    cudaGetSymbolAddress((void**)&W1T,  g_W1T);
    cudaGetSymbolAddress((void**)&W2T,  g_W2T);

    const int G128_SMEM = 2 * 128 * P1 * 2;   // 69632
    cudaFuncSetAttribute(gemm128<1, 1>, cudaFuncAttributeMaxDynamicSharedMemorySize, G128_SMEM);
    cudaFuncSetAttribute(gemm128<0, 0>, cudaFuncAttributeMaxDynamicSharedMemorySize, G128_SMEM);
    cudaFuncSetAttribute(gemm_big<1, 1>, cudaFuncAttributeMaxDynamicSharedMemorySize, BIG_SMEM);
    cudaFuncSetAttribute(gemm_big<0, 0>, cudaFuncAttributeMaxDynamicSharedMemorySize, BIG_SMEM);
    cudaFuncSetAttribute(attn_mma, cudaFuncAttributeMaxDynamicSharedMemorySize, AT_SMEM_BYTES);

    // 1) all weight transposes in one launch (fp32 -> fp16 [N,K])
    transpose_all<<<448, dim3(32, 8)>>>(Wq, Wk, Wv, Wm, W1, W2);

    // 2) Q projection (window-permute fused into A load)
    gemm128<1, 1><<<dim3(1, 256), 256, G128_SMEM>>>(src, WqT, QW, QW);

    // 3) K+V projections in one launch (B = [WkT;WvT], grid.x selects output)
    gemm128<1, 1><<<dim3(2, 256), 256, G128_SMEM>>>(tgt, WkvT, KW, VW);

    // 4) per-window V transpose
    vtrans_kernel<<<dim3(4, 8, 128), dim3(32, 8)>>>();

    // 5) shifted-window attention (fp16 mma.sync)
    attn_mma<<<4 * BB * NWIN, 256, AT_SMEM_BYTES>>>();

    // 6) message projection (fp32 out -> LayerNorm)
    gemm128<0, 0><<<dim3(1, 256), 256, G128_SMEM>>>(ATT, WmT, MSG, MSG);

    // 7) LN(msg) + un-shift + concat (fp16 out)
    ln_concat_kernel<<<4096, 256>>>(src, g1, b1);

    // 8) FFN
    gemm_big<1, 1><<<dim3(8, 256), 256, BIG_SMEM>>>(FIN, W1T, HIDp, HIDN, 2 * CC);
    gemm_big<0, 0><<<dim3(1, 256), 256, BIG_SMEM>>>(HIDp, W2T, MSG2, CC, HIDN);

    // 9) final LN + residual
    ln_res_kernel<<<4096, 256>>>(src, g2, b2, (float*)d_out);
}

// round 8
// speedup vs baseline: 4.2254x; 1.0001x over previous
#include <cuda_runtime.h>
#include <cuda_fp16.h>
#include <math.h>
#include <stdint.h>

// Problem constants
#define BB   2
#define HH   128
#define WWID 128
#define CC   128
#define NWIN 64
#define WSZ  256
#define LTOK (HH*WWID)     // 16384
#define ROWS (BB*LTOK)     // 32768
#define HIDN 1024

// ---------------- scratch ---------------------------------------------------
__device__ __half g_QW[ROWS*CC];
__device__ __half g_KW[ROWS*CC];
__device__ __half g_VW[ROWS*CC];
__device__ __half g_VWt[ROWS*CC];          // per-window transposed V: [wb][dim][key]
__device__ __half g_ATT[ROWS*CC];
__device__ float  g_MSG[ROWS*CC];          // fp32 (feeds LayerNorm)
__device__ __half g_FIN[(size_t)ROWS*2*CC];
__device__ __half g_HID[(size_t)ROWS*HIDN];
__device__ float  g_MSG2[ROWS*CC];         // fp32 (feeds LayerNorm)
// transposed weights [N, K] in fp16
__device__ __half g_WqT[CC*CC];
__device__ __half g_WkvT[2*CC*CC];         // [WkT ; WvT]
__device__ __half g_WmT[CC*CC];
__device__ __half g_W1T[HIDN*2*CC];
__device__ __half g_W2T[CC*HIDN];

// ---------------- helpers ---------------------------------------------------
__device__ __forceinline__ float gelu_exact(float x) {
    return 0.5f * x * (1.0f + erff(x * 0.70710678118654752f));
}
__device__ __forceinline__ uint32_t smem_u32(const void* p) {
    uint32_t a;
    asm("{ .reg .u64 t; cvta.to.shared.u64 t, %1; cvt.u32.u64 %0, t; }" : "=r"(a) : "l"(p));
    return a;
}
__device__ __forceinline__ void cpasync16(uint32_t dst, const __half* src) {
    asm volatile("cp.async.cg.shared.global [%0], [%1], 16;" :: "r"(dst), "l"(src));
}
#define CP_COMMIT() asm volatile("cp.async.commit_group;")
#define CP_WAIT0()  asm volatile("cp.async.wait_group 0;")
__device__ __forceinline__ void ldmx4(uint32_t addr, uint32_t& d0, uint32_t& d1,
                                      uint32_t& d2, uint32_t& d3) {
    asm volatile("ldmatrix.sync.aligned.m8n8.x4.shared.b16 {%0,%1,%2,%3}, [%4];"
                 : "=r"(d0), "=r"(d1), "=r"(d2), "=r"(d3) : "r"(addr));
}
__device__ __forceinline__ void mma_h(float* c, const uint32_t* a, uint32_t b0, uint32_t b1) {
    asm volatile("mma.sync.aligned.m16n8k16.row.col.f32.f16.f16.f32 "
                 "{%0,%1,%2,%3}, {%4,%5,%6,%7}, {%8,%9}, {%0,%1,%2,%3};"
                 : "+f"(c[0]), "+f"(c[1]), "+f"(c[2]), "+f"(c[3])
                 : "r"(a[0]), "r"(a[1]), "r"(a[2]), "r"(a[3]), "r"(b0), "r"(b1));
}

// ---------------- batched weight transpose: fp32 [R,C] -> fp16 [C,R] --------
__global__ __launch_bounds__(256) void transpose_all(const float* __restrict__ Wq,
                                                     const float* __restrict__ Wk,
                                                     const float* __restrict__ Wv,
                                                     const float* __restrict__ Wm,
                                                     const float* __restrict__ W1,
                                                     const float* __restrict__ W2)
{
    __shared__ float t[32][33];
    int id = blockIdx.x;
    const float* src; __half* dst; int R, C, bx, by;
    if (id < 64) {
        int wsel = id >> 4, tt = id & 15;
        bx = tt & 3; by = tt >> 2; R = 128; C = 128;
        src = (wsel == 0) ? Wq : (wsel == 1) ? Wk : (wsel == 2) ? Wv : Wm;
        dst = (wsel == 0) ? g_WqT : (wsel == 1) ? g_WkvT
            : (wsel == 2) ? (g_WkvT + 128 * 128) : g_WmT;
    } else if (id < 320) {
        int tt = id - 64; bx = tt & 31; by = tt >> 5; R = 256; C = 1024;
        src = W1; dst = g_W1T;
    } else {
        int tt = id - 320; bx = tt & 3; by = tt >> 2; R = 1024; C = 128;
        src = W2; dst = g_W2T;
    }
    int tx = threadIdx.x, ty = threadIdx.y;
    int x = bx * 32 + tx;
    #pragma unroll
    for (int i = 0; i < 32; i += 8)
        t[ty + i][tx] = src[(size_t)(by * 32 + ty + i) * C + x];
    __syncthreads();
    int x2 = by * 32 + tx;
    #pragma unroll
    for (int i = 0; i < 32; i += 8)
        dst[(size_t)(bx * 32 + ty + i) * R + x2] = __float2half(t[tx][ty + i]);
}

// ---------------- per-window V transpose (fp16) -----------------------------
__global__ __launch_bounds__(256) void vtrans_kernel()
{
    __shared__ __half t[32][34];
    int wb = blockIdx.z;
    int d0 = blockIdx.x * 32, k0 = blockIdx.y * 32;
    int tx = threadIdx.x, ty = threadIdx.y;
    const __half* src = g_VW + (size_t)wb * 32768;
    #pragma unroll
    for (int i = 0; i < 32; i += 8)
        t[ty + i][tx] = src[(size_t)(k0 + ty + i) * 128 + d0 + tx];
    __syncthreads();
    __half* dst = g_VWt + (size_t)wb * 32768;
    #pragma unroll
    for (int i = 0; i < 32; i += 8)
        dst[(size_t)(d0 + ty + i) * 256 + k0 + tx] = t[tx][ty + i];
}

// ---------------- one-shot K=128 GEMM ---------------------------------------
// PERM: 1 = A fp32 token layout, window-permuted rows; 0 = A fp16 windowed.
// OUTH: 1 = fp16 out; 0 = fp32 out.
#define P1 136
#define G128_SMEM (2*128*P1*2)   // 69632

template<int PERM, int OUTH>
__global__ __launch_bounds__(256, 2) void gemm128(const void* __restrict__ Av,
                                                  const __half* __restrict__ Bt,
                                                  void* __restrict__ C0v,
                                                  void* __restrict__ C1v)
{
    extern __shared__ __half smh[];
    __half* sA  = smh;             // [128][136]
    __half* sBt = smh + 128 * P1;  // [128][136]
    int tid = threadIdx.x, wid = tid >> 5, lane = tid & 31;
    int wm = wid & 3, wn = wid >> 2;
    size_t m0 = (size_t)blockIdx.y * 128;
    int nb = blockIdx.x;

    #pragma unroll
    for (int i = 0; i < 8; i++) {
        int idx = tid + i * 256;
        int row = idx >> 4, c8 = (idx & 15) * 8;
        cpasync16(smem_u32(sBt + row * P1 + c8),
                  Bt + (size_t)(nb * 128 + row) * 128 + c8);
    }
    CP_COMMIT();

    if (PERM) {
        const float* Af = (const float*)Av;
        int r2 = tid >> 1, hh = tid & 1;
        size_t m = m0 + r2;
        int b = (int)(m >> 14), win = (int)((m >> 8) & 63), pos = (int)(m & 255);
        int ip = ((win >> 3) << 4) + (pos >> 4);
        int jp = ((win & 7) << 4) + (pos & 15);
        int ii = (ip + 8) & 127, jj = (jp + 8) & 127;
        const float* srow = Af + ((size_t)b * LTOK + (size_t)ii * 128 + jj) * 128 + hh * 64;
        __half* drow = sA + r2 * P1 + hh * 64;
        #pragma unroll
        for (int q = 0; q < 16; q++) {
            float4 v = *(const float4*)(srow + q * 4);
            *(__half2*)(drow + q * 4)     = __floats2half2_rn(v.x, v.y);
            *(__half2*)(drow + q * 4 + 2) = __floats2half2_rn(v.z, v.w);
        }
    } else {
        const __half* Ah = (const __half*)Av;
        #pragma unroll
        for (int i = 0; i < 8; i++) {
            int idx = tid + i * 256;
            int row = idx >> 4, c8 = (idx & 15) * 8;
            cpasync16(smem_u32(sA + row * P1 + c8), Ah + (m0 + row) * 128 + c8);
        }
        CP_COMMIT();
    }
    CP_WAIT0();
    __syncthreads();

    float acc[2][8][4] = {};
    int mat = lane >> 3, mr = lane & 7;
    int a_row = wm * 32 + (mat & 1) * 8 + mr;
    int a_k8  = (mat >> 1) * 8;
    int b_n   = wn * 64 + (mat >> 1) * 8 + mr;
    int b_k8  = (mat & 1) * 8;
    uint32_t uA = smem_u32(sA), uB = smem_u32(sBt);

    #pragma unroll
    for (int ks = 0; ks < 8; ks++) {
        uint32_t a[2][4], bb[4][4];
        #pragma unroll
        for (int mt = 0; mt < 2; mt++)
            ldmx4(uA + (uint32_t)(((a_row + mt * 16) * P1 + ks * 16 + a_k8) * 2),
                  a[mt][0], a[mt][1], a[mt][2], a[mt][3]);
        #pragma unroll
        for (int h = 0; h < 4; h++)
            ldmx4(uB + (uint32_t)(((b_n + h * 16) * P1 + ks * 16 + b_k8) * 2),
                  bb[h][0], bb[h][1], bb[h][2], bb[h][3]);
        #pragma unroll
        for (int mt = 0; mt < 2; mt++)
            #pragma unroll
            for (int nt = 0; nt < 8; nt++)
                mma_h(acc[mt][nt], a[mt],
                      bb[nt >> 1][(nt & 1) * 2], bb[nt >> 1][(nt & 1) * 2 + 1]);
    }

    void* Cv = (nb == 0) ? C0v : C1v;
    int er = lane >> 2, ec = (lane & 3) * 2;
    #pragma unroll
    for (int mt = 0; mt < 2; mt++) {
        size_t r0 = m0 + wm * 32 + mt * 16 + er;
        #pragma unroll
        for (int nt = 0; nt < 8; nt++) {
            int c0 = wn * 64 + nt * 8 + ec;
            if (OUTH) {
                __half* C = (__half*)Cv;
                *(__half2*)(C + r0 * 128 + c0) =
                    __floats2half2_rn(acc[mt][nt][0], acc[mt][nt][1]);
                *(__half2*)(C + (r0 + 8) * 128 + c0) =
                    __floats2half2_rn(acc[mt][nt][2], acc[mt][nt][3]);
            } else {
                float* C = (float*)Cv;
                *(float2*)(C + r0 * 128 + c0) =
                    make_float2(acc[mt][nt][0], acc[mt][nt][1]);
                *(float2*)(C + (r0 + 8) * 128 + c0) =
                    make_float2(acc[mt][nt][2], acc[mt][nt][3]);
            }
        }
    }
}

// ---------------- big-K GEMM: 2-stage cp.async, K-chunk 64 ------------------
// smem = 2 stages * (A+B) * 128*72 halves * 2B = 73728 -> true 2 CTAs/SM.
#define P2 72
#define ST_ELEMS (128*P2)
#define BIG_SMEM (2*2*ST_ELEMS*2)   // 73728

__device__ __forceinline__ void big_load_stage(__half* smh, int s,
                                               const __half* __restrict__ A,
                                               const __half* __restrict__ Bt,
                                               size_t m0, int n0, int K, int kc, int tid)
{
    __half* dA = smh + s * 2 * ST_ELEMS;
    __half* dB = dA + ST_ELEMS;
    #pragma unroll
    for (int i = 0; i < 4; i++) {
        int idx = tid + i * 256;
        int row = idx >> 3, c8 = (idx & 7) * 8;
        cpasync16(smem_u32(dA + row * P2 + c8), A  + (m0 + row) * (size_t)K + kc * 64 + c8);
        cpasync16(smem_u32(dB + row * P2 + c8), Bt + (size_t)(n0 + row) * K + kc * 64 + c8);
    }
    CP_COMMIT();
}

template<int OUTH, int ACT>
__global__ __launch_bounds__(256, 2) void gemm_big(const __half* __restrict__ A,
                                                   const __half* __restrict__ Bt,
                                                   void* __restrict__ Cv,
                                                   int N, int K)
{
    extern __shared__ __half smh[];
    int tid = threadIdx.x, wid = tid >> 5, lane = tid & 31;
    int wm = wid & 3, wn = wid >> 2;
    size_t m0 = (size_t)blockIdx.y * 128;
    int n0 = blockIdx.x * 128;
    const int nk = K >> 6;

    big_load_stage(smh, 0, A, Bt, m0, n0, K, 0, tid);

    float acc[2][8][4] = {};
    int mat = lane >> 3, mr = lane & 7;
    int a_row = wm * 32 + (mat & 1) * 8 + mr;
    int a_k8  = (mat >> 1) * 8;
    int b_n   = wn * 64 + (mat >> 1) * 8 + mr;
    int b_k8  = (mat & 1) * 8;

    for (int kt = 0; kt < nk; kt++) {
        CP_WAIT0();
        __syncthreads();
        if (kt + 1 < nk)
            big_load_stage(smh, (kt + 1) & 1, A, Bt, m0, n0, K, kt + 1, tid);

        int s = kt & 1;
        uint32_t uA = smem_u32(smh + s * 2 * ST_ELEMS);
        uint32_t uB = smem_u32(smh + s * 2 * ST_ELEMS + ST_ELEMS);
        #pragma unroll
        for (int ks = 0; ks < 4; ks++) {
            uint32_t a[2][4], bb[4][4];
            #pragma unroll
            for (int mt = 0; mt < 2; mt++)
                ldmx4(uA + (uint32_t)(((a_row + mt * 16) * P2 + ks * 16 + a_k8) * 2),
                      a[mt][0], a[mt][1], a[mt][2], a[mt][3]);
            #pragma unroll
            for (int h = 0; h < 4; h++)
                ldmx4(uB + (uint32_t)(((b_n + h * 16) * P2 + ks * 16 + b_k8) * 2),
                      bb[h][0], bb[h][1], bb[h][2], bb[h][3]);
            #pragma unroll
            for (int mt = 0; mt < 2; mt++)
                #pragma unroll
                for (int nt = 0; nt < 8; nt++)
                    mma_h(acc[mt][nt], a[mt],
                          bb[nt >> 1][(nt & 1) * 2], bb[nt >> 1][(nt & 1) * 2 + 1]);
        }
        __syncthreads();
    }

    int er = lane >> 2, ec = (lane & 3) * 2;
    #pragma unroll
    for (int mt = 0; mt < 2; mt++) {
        size_t r0 = m0 + wm * 32 + mt * 16 + er;
        #pragma unroll
        for (int nt = 0; nt < 8; nt++) {
            int c0 = n0 + wn * 64 + nt * 8 + ec;
            float v0 = acc[mt][nt][0], v1 = acc[mt][nt][1];
            float v2 = acc[mt][nt][2], v3 = acc[mt][nt][3];
            if (ACT) {
                v0 = gelu_exact(v0); v1 = gelu_exact(v1);
                v2 = gelu_exact(v2); v3 = gelu_exact(v3);
            }
            if (OUTH) {
                __half* C = (__half*)Cv;
                *(__half2*)(C + r0 * N + c0)       = __floats2half2_rn(v0, v1);
                *(__half2*)(C + (r0 + 8) * N + c0) = __floats2half2_rn(v2, v3);
            } else {
                float* C = (float*)Cv;
                *(float2*)(C + r0 * N + c0)       = make_float2(v0, v1);
                *(float2*)(C + (r0 + 8) * N + c0) = make_float2(v2, v3);
            }
        }
    }
}

// ---------------- windowed attention via fp16 mma.sync ----------------------
#define AQ 0
#define AK 17408
#define AS 35840
#define AP 102400
#define AI 136192
#define AT_SMEM_BYTES 136448

__device__ __forceinline__ int region3(int x) { return (x < 112) ? 0 : ((x < 120) ? 1 : 2); }
__device__ __forceinline__ int posid(int p, int wr, int wc) {
    return region3(wr * 16 + (p >> 4)) * 3 + region3(wc * 16 + (p & 15));
}

__global__ __launch_bounds__(256) void attn_mma()
{
    extern __shared__ char sm[];
    uint32_t sB = smem_u32(sm);
    __half* Qs = (__half*)(sm + AQ);
    __half* KVs = (__half*)(sm + AK);
    float*  Ss = (float*)(sm + AS);
    __half* Ps = (__half*)(sm + AP);
    float*  Is = (float*)(sm + AI);

    const int tid = threadIdx.x;
    const int lane = tid & 31, w = tid >> 5;
    const int wb = blockIdx.x >> 2, quar = blockIdx.x & 3;
    const int q0 = quar * 64;
    const int win = wb & 63, wr = win >> 3, wc = win & 7;
    const size_t wbase = (size_t)wb * 256 * 128;

    const int wm = w & 3, wn = w >> 2;
    const int mat = lane >> 3, mr = lane & 7;
    const int a_row = wm * 16 + (mat & 1) * 8 + mr;
    const int a_k8  = (mat >> 1) * 8;
    const int bn_off = (mat >> 1) * 8 + mr;
    const int b_k8   = (mat & 1) * 8;
    const int er = lane >> 2, ec = (lane & 3) * 2;

    {
        #pragma unroll
        for (int i = 0; i < 4; i++) {
            int idx = tid + i * 256;
            int row = idx >> 4, c8 = (idx & 15) * 8;
            *(uint4*)(Qs + row * 136 + c8) =
                *(const uint4*)(g_QW + wbase + (size_t)(q0 + row) * 128 + c8);
        }
    }

    const int rq = wm * 16 + er;
    const int idq0 = posid(q0 + rq, wr, wc);
    const int idq1 = posid(q0 + rq + 8, wr, wc);
    const float SC = 0.08838834764831845f;

    for (int kb = 0; kb < 4; kb++) {
        __syncthreads();
        #pragma unroll
        for (int i = 0; i < 4; i++) {
            int idx = tid + i * 256;
            int row = idx >> 4, c8 = (idx & 15) * 8;
            *(uint4*)(KVs + row * 136 + c8) =
                *(const uint4*)(g_KW + wbase + (size_t)(kb * 64 + row) * 128 + c8);
        }
        __syncthreads();

        float sacc[4][4];
        #pragma unroll
        for (int nt = 0; nt < 4; nt++)
            #pragma unroll
            for (int i = 0; i < 4; i++) sacc[nt][i] = 0.f;

        #pragma unroll
        for (int ks = 0; ks < 8; ks++) {
            uint32_t a[4], bbf[2][4];
            ldmx4(sB + (uint32_t)(AQ + (a_row * 136 + ks * 16 + a_k8) * 2),
                  a[0], a[1], a[2], a[3]);
            #pragma unroll
            for (int h = 0; h < 2; h++)
                ldmx4(sB + (uint32_t)(AK + ((wn * 32 + h * 16 + bn_off) * 136 + ks * 16 + b_k8) * 2),
                      bbf[h][0], bbf[h][1], bbf[h][2], bbf[h][3]);
            #pragma unroll
            for (int nt = 0; nt < 4; nt++)
                mma_h(sacc[nt], a, bbf[nt >> 1][(nt & 1) * 2], bbf[nt >> 1][(nt & 1) * 2 + 1]);
        }

        #pragma unroll
        for (int nt = 0; nt < 4; nt++) {
            int key = kb * 64 + wn * 32 + nt * 8 + ec;
            int idk0 = posid(key, wr, wc), idk1 = posid(key + 1, wr, wc);
            float2 v0, v1;
            v0.x = sacc[nt][0] * SC + ((idq0 == idk0) ? 0.f : -100.f);
            v0.y = sacc[nt][1] * SC + ((idq0 == idk1) ? 0.f : -100.f);
            v1.x = sacc[nt][2] * SC + ((idq1 == idk0) ? 0.f : -100.f);
            v1.y = sacc[nt][3] * SC + ((idq1 == idk1) ? 0.f : -100.f);
            *(float2*)(Ss + rq * 260 + key)       = v0;
            *(float2*)(Ss + (rq + 8) * 260 + key) = v1;
        }
    }
    __syncthreads();

    {
        int row = tid >> 2, sub = tid & 3;
        float* sr = Ss + row * 260 + sub;
        __half* pr = Ps + row * 264 + sub;
        float mx = -1e30f;
        #pragma unroll 8
        for (int i = 0; i < 64; i++) mx = fmaxf(mx, sr[i * 4]);
        mx = fmaxf(mx, __shfl_xor_sync(0xffffffffu, mx, 1));
        mx = fmaxf(mx, __shfl_xor_sync(0xffffffffu, mx, 2));
        float s = 0.f;
        #pragma unroll 8
        for (int i = 0; i < 64; i++) {
            float p = __expf(sr[i * 4] - mx);
            pr[i * 4] = __float2half(p);
            s += p;
        }
        s += __shfl_xor_sync(0xffffffffu, s, 1);
        s += __shfl_xor_sync(0xffffffffu, s, 2);
        if (sub == 0) Is[row] = 1.0f / s;
    }

    float oacc[8][4];
    #pragma unroll
    for (int nt = 0; nt < 8; nt++)
        #pragma unroll
        for (int i = 0; i < 4; i++) oacc[nt][i] = 0.f;

    for (int kb = 0; kb < 4; kb++) {
        __syncthreads();
        #pragma unroll
        for (int i = 0; i < 4; i++) {
            int idx = tid + i * 256;
            int row = idx >> 3, c8 = (idx & 7) * 8;
            *(uint4*)(KVs + row * 72 + c8) =
                *(const uint4*)(g_VWt + (size_t)wb * 32768 + (size_t)row * 256 + kb * 64 + c8);
        }
        __syncthreads();

        #pragma unroll
        for (int ks = 0; ks < 4; ks++) {
            uint32_t a[4], bv[4][4];
            ldmx4(sB + (uint32_t)(AP + (a_row * 264 + kb * 64 + ks * 16 + a_k8) * 2),
                  a[0], a[1], a[2], a[3]);
            #pragma unroll
            for (int h = 0; h < 4; h++)
                ldmx4(sB + (uint32_t)(AK + ((wn * 64 + h * 16 + bn_off) * 72 + ks * 16 + b_k8) * 2),
                      bv[h][0], bv[h][1], bv[h][2], bv[h][3]);
            #pragma unroll
            for (int nt = 0; nt < 8; nt++)
                mma_h(oacc[nt], a, bv[nt >> 1][(nt & 1) * 2], bv[nt >> 1][(nt & 1) * 2 + 1]);
        }
    }

    {
        float i0 = Is[rq], i1 = Is[rq + 8];
        __half* op = g_ATT + wbase + (size_t)(q0 + rq) * 128;
        #pragma unroll
        for (int nt = 0; nt < 8; nt++) {
            int dim = wn * 64 + nt * 8 + ec;
            *(__half2*)(op + dim) =
                __floats2half2_rn(oacc[nt][0] * i0, oacc[nt][1] * i0);
            *(__half2*)(op + 8 * 128 + dim) =
                __floats2half2_rn(oacc[nt][2] * i1, oacc[nt][3] * i1);
        }
    }
}

// ---------------- LN(msg) + un-shift gather + concat (fp16 out) -------------
__global__ __launch_bounds__(256) void ln_concat_kernel(const float* __restrict__ src,
                                                        const float* __restrict__ g1,
                                                        const float* __restrict__ b1)
{
    int warp = (blockIdx.x * 256 + threadIdx.x) >> 5;
    int lane = threadIdx.x & 31;
    if (warp >= ROWS) return;
    int b   = warp >> 14;
    int tok = warp & 16383;
    int i = tok >> 7, j = tok & 127;
    int ip = (i + 120) & 127;
    int jp = (j + 120) & 127;
    int win = ((ip >> 4) << 3) + (jp >> 4);
    int pos = ((ip & 15) << 4) + (jp & 15);
    size_t mrow = ((size_t)b * NWIN + win) * WSZ + pos;

    float4 mv = ((const float4*)(g_MSG + mrow * CC))[lane];
    float s  = mv.x + mv.y + mv.z + mv.w;
    float ss = mv.x * mv.x + mv.y * mv.y + mv.z * mv.z + mv.w * mv.w;
    #pragma unroll
    for (int o = 16; o > 0; o >>= 1) {
        s  += __shfl_xor_sync(0xffffffffu, s,  o);
        ss += __shfl_xor_sync(0xffffffffu, ss, o);
    }
    float mean = s * (1.0f / 128.0f);
    float var  = ss * (1.0f / 128.0f) - mean * mean;
    float r = rsqrtf(var + 1e-5f);
    float4 gv = ((const float4*)g1)[lane];
    float4 bv = ((const float4*)b1)[lane];
    float o0 = (mv.x - mean) * r * gv.x + bv.x;
    float o1 = (mv.y - mean) * r * gv.y + bv.y;
    float o2 = (mv.z - mean) * r * gv.z + bv.z;
    float o3 = (mv.w - mean) * r * gv.w + bv.w;

    float4 sv = ((const float4*)(src + (size_t)warp * CC))[lane];

    __half* frow = g_FIN + (size_t)warp * (2 * CC);
    ((__half2*)(frow))[lane * 2]           = __floats2half2_rn(sv.x, sv.y);
    ((__half2*)(frow))[lane * 2 + 1]       = __floats2half2_rn(sv.z, sv.w);
    ((__half2*)(frow + CC))[lane * 2]      = __floats2half2_rn(o0, o1);
    ((__half2*)(frow + CC))[lane * 2 + 1]  = __floats2half2_rn(o2, o3);
}

// ---------------- final LN + residual ---------------------------------------
__global__ __launch_bounds__(256) void ln_res_kernel(const float* __restrict__ src,
                                                     const float* __restrict__ g2,
                                                     const float* __restrict__ b2,
                                                     float* __restrict__ out)
{
    int warp = (blockIdx.x * 256 + threadIdx.x) >> 5;
    int lane = threadIdx.x & 31;
    if (warp >= ROWS) return;

    float4 mv = ((const float4*)(g_MSG2 + (size_t)warp * CC))[lane];
    float s  = mv.x + mv.y + mv.z + mv.w;
    float ss = mv.x * mv.x + mv.y * mv.y + mv.z * mv.z + mv.w * mv.w;
    #pragma unroll
    for (int o = 16; o > 0; o >>= 1) {
        s  += __shfl_xor_sync(0xffffffffu, s,  o);
        ss += __shfl_xor_sync(0xffffffffu, ss, o);
    }
    float mean = s * (1.0f / 128.0f);
    float var  = ss * (1.0f / 128.0f) - mean * mean;
    float r = rsqrtf(var + 1e-5f);
    float4 gv = ((const float4*)g2)[lane];
    float4 bv = ((const float4*)b2)[lane];
    float4 sv = ((const float4*)(src + (size_t)warp * CC))[lane];
    float4 o4;
    o4.x = sv.x + (mv.x - mean) * r * gv.x + bv.x;
    o4.y = sv.y + (mv.y - mean) * r * gv.y + bv.y;
    o4.z = sv.z + (mv.z - mean) * r * gv.z + bv.z;
    o4.w = sv.w + (mv.w - mean) * r * gv.w + bv.w;
    ((float4*)(out + (size_t)warp * CC))[lane] = o4;
}

// ---------------- host launcher ---------------------------------------------
extern "C" void kernel_launch(void* const* d_in, const int* in_sizes, int n_in,
                              void* d_out, int out_size)
{
    const float* src = (const float*)d_in[0];
    const float* tgt = (const float*)d_in[1];
    const float* Wq  = (const float*)d_in[2];
    const float* Wk  = (const float*)d_in[3];
    const float* Wv  = (const float*)d_in[4];
    const float* Wm  = (const float*)d_in[5];
    const float* g1  = (const float*)d_in[6];
    const float* b1  = (const float*)d_in[7];
    const float* W1  = (const float*)d_in[8];
    const float* W2  = (const float*)d_in[9];
    const float* g2  = (const float*)d_in[10];
    const float* b2  = (const float*)d_in[11];

    __half *QW, *KW, *VW, *ATT, *FIN, *HIDp;
    __half *WqT, *WkvT, *WmT, *W1T, *W2T;
    float *MSG, *MSG2;
    cudaGetSymbolAddress((void**)&QW,   g_QW);
    cudaGetSymbolAddress((void**)&KW,   g_KW);
    cudaGetSymbolAddress((void**)&VW,   g_VW);
    cudaGetSymbolAddress((void**)&ATT,  g_ATT);
    cudaGetSymbolAddress((void**)&MSG,  g_MSG);
    cudaGetSymbolAddress((void**)&FIN,  g_FIN);
    cudaGetSymbolAddress((void**)&HIDp, g_HID);
    cudaGetSymbolAddress((void**)&MSG2, g_MSG2);
    cudaGetSymbolAddress((void**)&WqT,  g_WqT);
    cudaGetSymbolAddress((void**)&WkvT, g_WkvT);
    cudaGetSymbolAddress((void**)&WmT,  g_WmT);
    cudaGetSymbolAddress((void**)&W1T,  g_W1T);
    cudaGetSymbolAddress((void**)&W2T,  g_W2T);

    cudaFuncSetAttribute(gemm128<1, 1>, cudaFuncAttributeMaxDynamicSharedMemorySize, G128_SMEM);
    cudaFuncSetAttribute(gemm128<0, 0>, cudaFuncAttributeMaxDynamicSharedMemorySize, G128_SMEM);
    cudaFuncSetAttribute(gemm_big<1, 1>, cudaFuncAttributeMaxDynamicSharedMemorySize, BIG_SMEM);
    cudaFuncSetAttribute(gemm_big<0, 0>, cudaFuncAttributeMaxDynamicSharedMemorySize, BIG_SMEM);
    cudaFuncSetAttribute(attn_mma, cudaFuncAttributeMaxDynamicSharedMemorySize, AT_SMEM_BYTES);

    // 1) all weight transposes in one launch (fp32 -> fp16 [N,K])
    transpose_all<<<448, dim3(32, 8)>>>(Wq, Wk, Wv, Wm, W1, W2);

    // 2) Q projection (window-permute fused into A load)
    gemm128<1, 1><<<dim3(1, 256), 256, G128_SMEM>>>(src, WqT, QW, QW);

    // 3) K+V projections in one launch (B = [WkT;WvT], grid.x selects output)
    gemm128<1, 1><<<dim3(2, 256), 256, G128_SMEM>>>(tgt, WkvT, KW, VW);

    // 4) per-window V transpose
    vtrans_kernel<<<dim3(4, 8, 128), dim3(32, 8)>>>();

    // 5) shifted-window attention (fp16 mma.sync)
    attn_mma<<<4 * BB * NWIN, 256, AT_SMEM_BYTES>>>();

    // 6) message projection (fp32 out -> LayerNorm)
    gemm128<0, 0><<<dim3(1, 256), 256, G128_SMEM>>>(ATT, WmT, MSG, MSG);

    // 7) LN(msg) + un-shift + concat (fp16 out)
    ln_concat_kernel<<<4096, 256>>>(src, g1, b1);

    // 8) FFN (2-stage pipelined, 2 CTAs/SM)
    gemm_big<1, 1><<<dim3(8, 256), 256, BIG_SMEM>>>(FIN, W1T, HIDp, HIDN, 2 * CC);
    gemm_big<0, 0><<<dim3(1, 256), 256, BIG_SMEM>>>(HIDp, W2T, MSG2, CC, HIDN);

    // 9) final LN + residual
    ln_res_kernel<<<4096, 256>>>(src, g2, b2, (float*)d_out);
}